// round 10
// baseline (speedup 1.0000x reference)
#include <cuda_runtime.h>
#include <math.h>
#include <stdint.h>

#define BB 4
#define LL 2048
#define DD 1024
#define DIN 1024
#define NS 8
#define RR 64
#define DBLW 80
#define SEG 32
#define SEGL (LL/SEG)     // 64
#define MTOT (BB*LL)
#define SPLITK 4

// ---------------- scratch ----------------
__device__ float g_xnorm[MTOT*DD];        // PERMUTED k-layout
__device__ float g_xz[MTOT*2*DIN];        // plain
__device__ float g_xconv[MTOT*DIN];       // PERMUTED
__device__ float g_dbl[MTOT*DBLW];        // plain
__device__ float g_dblp[SPLITK*MTOT*DBLW];
__device__ float g_dt[MTOT*DIN];          // plain
__device__ float g_y[MTOT*DIN];           // PERMUTED
__device__ float g_segA[BB*SEG*NS*DIN];
__device__ float g_segB[BB*SEG*NS*DIN];
__device__ float g_hin[BB*SEG*NS*DIN];
__device__ float g_w_in[2*DIN*DD];        // PERMUTED
__device__ float g_w_x[DBLW*DIN];         // PERMUTED
__device__ float g_w_dt[DIN*RR];          // plain
__device__ float g_w_out[DD*DIN];         // PERMUTED

// k-permutation within each 8-group: position of k is 2*(k&3) + (k>>2)
// (so positions (2t, 2t+1) hold (k=t, k=t+4) — the tf32 fragment pair)
__device__ __forceinline__ int permpos(int d) {
    return (d & ~7) | (((d & 3) << 1) | ((d >> 2) & 1));
}

// ---------------- helpers ----------------
__device__ __forceinline__ float rnd_tf32(float f) {
    uint32_t u;
    asm("cvt.rna.tf32.f32 %0, %1;" : "=r"(u) : "f"(f));
    return __uint_as_float(u);
}

__device__ __forceinline__ void mma_tf32(float c[4], const uint32_t a[4], const uint32_t b[2]) {
    asm volatile(
        "mma.sync.aligned.m16n8k8.row.col.f32.tf32.tf32.f32 "
        "{%0,%1,%2,%3}, {%4,%5,%6,%7}, {%8,%9}, {%0,%1,%2,%3};"
        : "+f"(c[0]), "+f"(c[1]), "+f"(c[2]), "+f"(c[3])
        : "r"(a[0]), "r"(a[1]), "r"(a[2]), "r"(a[3]), "r"(b[0]), "r"(b[1]));
}

__device__ __forceinline__ void cp16(uint32_t dst, const void* src, bool v) {
    int sz = v ? 16 : 0;
    asm volatile("cp.async.cg.shared.global [%0], [%1], 16, %2;\n"
                 :: "r"(dst), "l"(src), "r"(sz));
}

// permute 8 consecutive floats (one k-group) into fragment-pair order
__device__ __forceinline__ void perm_store8(float4* dst2, const float o[8]) {
    dst2[0] = make_float4(o[0], o[4], o[1], o[5]);
    dst2[1] = make_float4(o[2], o[6], o[3], o[7]);
}

// ---------------- weight convert ----------------
#define NWI (2*DIN*DD)
#define NWX (DBLW*DIN)
#define NWDT (DIN*RR)
#define NWO (DD*DIN)

__global__ __launch_bounds__(256) void cvt_weights_big(const float4* __restrict__ iw,
                                                       const float4* __restrict__ ow) {
    int i = blockIdx.x * 256 + threadIdx.x;   // one 8-float k-group per thread
    const float4* src;
    float4* dst;
    if (i < NWI/8) { src = iw + 2*i; dst = (float4*)g_w_in + 2*i; }
    else if ((i -= NWI/8) < NWO/8) { src = ow + 2*i; dst = (float4*)g_w_out + 2*i; }
    else return;
    const float4 a = src[0], b = src[1];
    float o[8] = {rnd_tf32(a.x), rnd_tf32(a.y), rnd_tf32(a.z), rnd_tf32(a.w),
                  rnd_tf32(b.x), rnd_tf32(b.y), rnd_tf32(b.z), rnd_tf32(b.w)};
    perm_store8(dst, o);
}

__global__ __launch_bounds__(256) void cvt_weights_small(const float4* __restrict__ xw,
                                                         const float4* __restrict__ dw) {
    int i = blockIdx.x * 256 + threadIdx.x;
    if (i < NWX/8) {   // w_x: permuted
        const float4 a = xw[2*i], b = xw[2*i + 1];
        float o[8] = {rnd_tf32(a.x), rnd_tf32(a.y), rnd_tf32(a.z), rnd_tf32(a.w),
                      rnd_tf32(b.x), rnd_tf32(b.y), rnd_tf32(b.z), rnd_tf32(b.w)};
        perm_store8((float4*)g_w_x + 2*i, o);
        return;
    }
    i -= NWX/8;
    if (i < NWDT/4) {  // w_dt: plain
        float4 v = dw[i];
        v.x = rnd_tf32(v.x); v.y = rnd_tf32(v.y);
        v.z = rnd_tf32(v.z); v.w = rnd_tf32(v.w);
        ((float4*)g_w_dt)[i] = v;
    }
}

// ---------------- RMSNorm (permuted output) ----------------
__global__ __launch_bounds__(128) void rmsnorm_kernel(const float* __restrict__ x,
                                                      const float* __restrict__ w) {
    const int row = blockIdx.x;
    const int t = threadIdx.x;                 // 128 threads x 8 floats
    const float4* xr4 = (const float4*)(x + (size_t)row * DD);
    const float4 v0 = xr4[2*t], v1 = xr4[2*t + 1];
    float ss = v0.x*v0.x + v0.y*v0.y + v0.z*v0.z + v0.w*v0.w
             + v1.x*v1.x + v1.y*v1.y + v1.z*v1.z + v1.w*v1.w;
#pragma unroll
    for (int o = 16; o > 0; o >>= 1) ss += __shfl_xor_sync(0xffffffffu, ss, o);
    __shared__ float red[4];
    if ((t & 31) == 0) red[t >> 5] = ss;
    __syncthreads();
    const float tot = red[0] + red[1] + red[2] + red[3];
    const float sc = rsqrtf(tot * (1.f / DD) + 1e-5f);
    const float4 w0 = ((const float4*)w)[2*t], w1 = ((const float4*)w)[2*t + 1];
    float o[8] = {rnd_tf32(v0.x * sc * w0.x), rnd_tf32(v0.y * sc * w0.y),
                  rnd_tf32(v0.z * sc * w0.z), rnd_tf32(v0.w * sc * w0.w),
                  rnd_tf32(v1.x * sc * w1.x), rnd_tf32(v1.y * sc * w1.y),
                  rnd_tf32(v1.z * sc * w1.z), rnd_tf32(v1.w * sc * w1.w)};
    perm_store8((float4*)(g_xnorm + (size_t)row * DD) + 2*t, o);
}

// ---------------- TF32 GEMM: BM=BN=128, BK=32, 256 thr, 8 warps 32x64 ----------------
// PERM=1: inputs in k-pair-permuted layout -> LDS.64 fragment loads
#define GSTAGES 3
#define GSTRIDE 36
#define STGF (128*GSTRIDE)
#define STGB (STGF*4)
#define GSMEM (2*GSTAGES*STGB)   // 110592 bytes

template<int PERM>
__global__ __launch_bounds__(256, 2) void gemm_tf32(
    const float* __restrict__ A, int lda,
    const float* __restrict__ W, int ldw,
    float* __restrict__ C, int ldc, size_t cstride,
    int K, int E,
    const float* __restrict__ bias, int epi)
{
    extern __shared__ float smem[];
    float* sA = smem;
    float* sB = smem + GSTAGES * STGF;

    const int tid = threadIdx.x;
    const int lane = tid & 31;
    const int wid = tid >> 5;
    const int m0 = blockIdx.y * 128;
    const int e0 = blockIdx.x * 128;
    const int z = blockIdx.z;
    const int mw = (wid & 3) * 32;
    const int nw = (wid >> 2) * 64;

    const int prow = tid >> 3;
    const int pk = (tid & 7) * 4;

    const float* aP[4];
    const float* wP[4];
    bool wv[4];
    uint32_t dAo[4], dBo[4];
    const uint32_t sAu = (uint32_t)__cvta_generic_to_shared(sA);
    const uint32_t sBu = (uint32_t)__cvta_generic_to_shared(sB);
#pragma unroll
    for (int c = 0; c < 4; c++) {
        const int r = prow + 32 * c;
        aP[c] = A + (size_t)(m0 + r) * lda + (size_t)z * K + pk;
        const int er = e0 + r;
        wv[c] = er < E;
        wP[c] = W + (size_t)(wv[c] ? er : 0) * ldw + (size_t)z * K + pk;
        dAo[c] = sAu + (r * GSTRIDE + pk) * 4;
        dBo[c] = sBu + (r * GSTRIDE + pk) * 4;
    }

    float acc[2][8][4];
#pragma unroll
    for (int i = 0; i < 2; i++)
#pragma unroll
        for (int j = 0; j < 8; j++)
#pragma unroll
            for (int l = 0; l < 4; l++) acc[i][j][l] = 0.f;

    const int T = K / 32;

#pragma unroll
    for (int p = 0; p < GSTAGES - 1; p++) {
        const int ko = p * 32;
#pragma unroll
        for (int c = 0; c < 4; c++) {
            cp16(dAo[c] + p * STGB, aP[c] + ko, true);
            cp16(dBo[c] + p * STGB, wP[c] + ko, wv[c]);
        }
        asm volatile("cp.async.commit_group;\n");
    }

    const int g = lane >> 2;
    const int tg = lane & 3;

    for (int t = 0; t < T; t++) {
        asm volatile("cp.async.wait_group 1;\n");
        __syncthreads();

        {
            const int tn = t + GSTAGES - 1;
            if (tn < T) {
                const int ko = tn * 32;
                const int so = tn % GSTAGES;
#pragma unroll
                for (int c = 0; c < 4; c++) {
                    cp16(dAo[c] + so * STGB, aP[c] + ko, true);
                    cp16(dBo[c] + so * STGB, wP[c] + ko, wv[c]);
                }
            }
            asm volatile("cp.async.commit_group;\n");
        }

        const int stg = t % GSTAGES;
        const float* At = sA + stg * STGF;
        const float* Bt = sB + stg * STGF;

#pragma unroll
        for (int ks = 0; ks < 4; ks++) {
            const int kk = ks * 8;
            uint32_t af[2][4];
            uint32_t bf[8][2];
            if (PERM) {
#pragma unroll
                for (int mt = 0; mt < 2; mt++) {
                    const int mb = mw + mt * 16 + g;
                    const float2 lo = *(const float2*)&At[mb * GSTRIDE + kk + 2 * tg];
                    const float2 hi = *(const float2*)&At[(mb + 8) * GSTRIDE + kk + 2 * tg];
                    af[mt][0] = __float_as_uint(lo.x);
                    af[mt][1] = __float_as_uint(hi.x);
                    af[mt][2] = __float_as_uint(lo.y);
                    af[mt][3] = __float_as_uint(hi.y);
                }
#pragma unroll
                for (int nt = 0; nt < 8; nt++) {
                    const int nb = nw + nt * 8 + g;
                    const float2 vb = *(const float2*)&Bt[nb * GSTRIDE + kk + 2 * tg];
                    bf[nt][0] = __float_as_uint(vb.x);
                    bf[nt][1] = __float_as_uint(vb.y);
                }
            } else {
#pragma unroll
                for (int mt = 0; mt < 2; mt++) {
                    const int mb = mw + mt * 16 + g;
                    af[mt][0] = __float_as_uint(At[mb * GSTRIDE + kk + tg]);
                    af[mt][1] = __float_as_uint(At[(mb + 8) * GSTRIDE + kk + tg]);
                    af[mt][2] = __float_as_uint(At[mb * GSTRIDE + kk + 4 + tg]);
                    af[mt][3] = __float_as_uint(At[(mb + 8) * GSTRIDE + kk + 4 + tg]);
                }
#pragma unroll
                for (int nt = 0; nt < 8; nt++) {
                    const int nb = nw + nt * 8 + g;
                    bf[nt][0] = __float_as_uint(Bt[nb * GSTRIDE + kk + tg]);
                    bf[nt][1] = __float_as_uint(Bt[nb * GSTRIDE + kk + 4 + tg]);
                }
            }
#pragma unroll
            for (int mt = 0; mt < 2; mt++)
#pragma unroll
                for (int nt = 0; nt < 8; nt++)
                    mma_tf32(acc[mt][nt], af[mt], bf[nt]);
        }
    }

    // epilogue (plain layout, float2 stores)
    float* Cz = C + (size_t)z * cstride;
#pragma unroll
    for (int mt = 0; mt < 2; mt++) {
        const int r0 = m0 + mw + mt * 16 + g;
        const int r1 = r0 + 8;
#pragma unroll
        for (int nt = 0; nt < 8; nt++) {
            const int c0 = e0 + nw + nt * 8 + tg * 2;
            if (c0 < E) {
                float va0 = acc[mt][nt][0], va1 = acc[mt][nt][1];
                float vb0 = acc[mt][nt][2], vb1 = acc[mt][nt][3];
                if (epi == 1) {
                    const float b0 = bias[c0], b1 = bias[c0 + 1];
                    va0 += b0; va0 = fmaxf(va0, 0.f) + log1pf(__expf(-fabsf(va0)));
                    va1 += b1; va1 = fmaxf(va1, 0.f) + log1pf(__expf(-fabsf(va1)));
                    vb0 += b0; vb0 = fmaxf(vb0, 0.f) + log1pf(__expf(-fabsf(vb0)));
                    vb1 += b1; vb1 = fmaxf(vb1, 0.f) + log1pf(__expf(-fabsf(vb1)));
                }
                *(float2*)(Cz + (size_t)r0 * ldc + c0) = make_float2(va0, va1);
                *(float2*)(Cz + (size_t)r1 * ldc + c0) = make_float2(vb0, vb1);
            }
        }
    }
}

// ---------------- split-K reduce for x_proj (plain layout) ----------------
__global__ __launch_bounds__(256) void reduce_dbl() {
    const int idx = blockIdx.x * 256 + threadIdx.x;
    if (idx >= MTOT * DBLW) return;
    float s = 0.f;
#pragma unroll
    for (int p = 0; p < SPLITK; p++) s += g_dblp[(size_t)p * MTOT * DBLW + idx];
    g_dbl[idx] = rnd_tf32(s);
}

// ---------------- conv+silu: 4 rows x 8 ch per thread, permuted output ----------------
__global__ __launch_bounds__(256) void conv_silu_kernel(const float* __restrict__ conv_w,
                                                        const float* __restrict__ conv_b) {
    const int t = blockIdx.x * 256 + threadIdx.x;
    const int nd8 = DIN / 8;                 // 128
    const int d0 = (t % nd8) * 8;
    const int m0 = (t / nd8) * 4;
    if (m0 >= MTOT) return;
    const int l0 = m0 % LL;
    const int b = m0 / LL;

    float4 xa[7], xb[7];
#pragma unroll
    for (int j = 0; j < 7; j++) {
        const int ls = l0 - 3 + j;
        if (ls >= 0) {
            const float* base = g_xz + ((size_t)(b * LL + ls)) * (2 * DIN) + d0;
            xa[j] = *(const float4*)base;
            xb[j] = *(const float4*)(base + 4);
        } else {
            xa[j] = make_float4(0.f, 0.f, 0.f, 0.f);
            xb[j] = xa[j];
        }
    }
    float4 wr[8];
#pragma unroll
    for (int c = 0; c < 8; c++) wr[c] = *(const float4*)(conv_w + (d0 + c) * 4);
    const float4 ba = *(const float4*)(conv_b + d0);
    const float4 bb = *(const float4*)(conv_b + d0 + 4);

#pragma unroll
    for (int i = 0; i < 4; i++) {
        float o[8];
        const float* w;
        // channels 0..3 from xa, 4..7 from xb
        o[0] = ba.x; o[1] = ba.y; o[2] = ba.z; o[3] = ba.w;
        o[4] = bb.x; o[5] = bb.y; o[6] = bb.z; o[7] = bb.w;
#pragma unroll
        for (int j = 0; j < 4; j++) {
            const float4 va = xa[i + j];
            const float4 vb = xb[i + j];
            o[0] += ((const float*)&wr[0])[j] * va.x;
            o[1] += ((const float*)&wr[1])[j] * va.y;
            o[2] += ((const float*)&wr[2])[j] * va.z;
            o[3] += ((const float*)&wr[3])[j] * va.w;
            o[4] += ((const float*)&wr[4])[j] * vb.x;
            o[5] += ((const float*)&wr[5])[j] * vb.y;
            o[6] += ((const float*)&wr[6])[j] * vb.z;
            o[7] += ((const float*)&wr[7])[j] * vb.w;
        }
#pragma unroll
        for (int c = 0; c < 8; c++) {
            const float s = o[c] / (1.f + __expf(-o[c]));
            o[c] = rnd_tf32(s);
        }
        perm_store8((float4*)(g_xconv + ((size_t)(m0 + i)) * DIN + d0), o);
    }
}

// ---------------- chunked selective scan (SEG=32) ----------------
__global__ __launch_bounds__(128) void scan_pass1(const float* __restrict__ A_log) {
    const int b = blockIdx.z;
    const int s = blockIdx.y;
    const int d = blockIdx.x * 128 + threadIdx.x;
    const int tid = threadIdx.x;
    const int l0 = s * SEGL;
    const int pd = permpos(d);

    float A[NS];
#pragma unroll
    for (int n = 0; n < NS; n++) A[n] = -__expf(A_log[d * NS + n]);

    float p[NS], h[NS];
#pragma unroll
    for (int n = 0; n < NS; n++) { p[n] = 1.f; h[n] = 0.f; }

    __shared__ float sB[SEGL][NS];
    for (int i = tid; i < SEGL * NS; i += 128) {
        const int ll = i >> 3;
        const int n = i & 7;
        sB[ll][n] = g_dbl[((size_t)(b * LL + l0 + ll)) * DBLW + RR + n];
    }
    __syncthreads();

    for (int j = 0; j < SEGL; j++) {
        const size_t rowb = ((size_t)(b * LL + l0 + j)) * DIN;
        const float dtv = g_dt[rowb + d];
        const float xv = g_xconv[rowb + pd];
        const float dtx = dtv * xv;
#pragma unroll
        for (int n = 0; n < NS; n++) {
            const float da = __expf(dtv * A[n]);
            p[n] *= da;
            h[n] = da * h[n] + dtx * sB[j][n];
        }
    }
#pragma unroll
    for (int n = 0; n < NS; n++) {
        const size_t o = ((size_t)((b * SEG + s) * NS + n)) * DIN + d;
        g_segA[o] = p[n];
        g_segB[o] = h[n];
    }
}

__global__ __launch_bounds__(256) void scan_pass2() {
    const int gidx = blockIdx.x * 256 + threadIdx.x;
    if (gidx >= BB * DIN) return;
    const int b = gidx / DIN;
    const int d = gidx % DIN;
    float h[NS];
#pragma unroll
    for (int n = 0; n < NS; n++) h[n] = 0.f;
    for (int s = 0; s < SEG; s++) {
#pragma unroll
        for (int n = 0; n < NS; n++) {
            const size_t o = ((size_t)((b * SEG + s) * NS + n)) * DIN + d;
            g_hin[o] = h[n];
            h[n] = g_segA[o] * h[n] + g_segB[o];
        }
    }
}

__global__ __launch_bounds__(128) void scan_pass3(const float* __restrict__ A_log,
                                                  const float* __restrict__ D_skip) {
    const int b = blockIdx.z;
    const int s = blockIdx.y;
    const int d = blockIdx.x * 128 + threadIdx.x;
    const int tid = threadIdx.x;
    const int l0 = s * SEGL;
    const int pd = permpos(d);

    float A[NS];
#pragma unroll
    for (int n = 0; n < NS; n++) A[n] = -__expf(A_log[d * NS + n]);
    const float dsk = D_skip[d];

    float h[NS];
#pragma unroll
    for (int n = 0; n < NS; n++)
        h[n] = g_hin[((size_t)((b * SEG + s) * NS + n)) * DIN + d];

    __shared__ float sB[SEGL][NS];
    __shared__ float sC[SEGL][NS];
    for (int i = tid; i < SEGL * NS * 2; i += 128) {
        const int ll = i >> 4;
        const int c = i & 15;
        const float v = g_dbl[((size_t)(b * LL + l0 + ll)) * DBLW + RR + c];
        if (c < NS) sB[ll][c] = v;
        else        sC[ll][c - NS] = v;
    }
    __syncthreads();

    for (int j = 0; j < SEGL; j++) {
        const size_t rowb = ((size_t)(b * LL + l0 + j)) * DIN;
        const float dtv = g_dt[rowb + d];
        const float xv = g_xconv[rowb + pd];
        const float dtx = dtv * xv;
        float yv = 0.f;
#pragma unroll
        for (int n = 0; n < NS; n++) {
            const float da = __expf(dtv * A[n]);
            h[n] = da * h[n] + dtx * sB[j][n];
            yv += h[n] * sC[j][n];
        }
        const float z = g_xz[((size_t)(b * LL + l0 + j)) * (2 * DIN) + DIN + d];
        const float sz = z / (1.f + __expf(-z));
        g_y[rowb + pd] = rnd_tf32((yv + dsk * xv) * sz);   // permuted for out_proj
    }
}

// ---------------- launch ----------------
extern "C" void kernel_launch(void* const* d_in, const int* in_sizes, int n_in,
                              void* d_out, int out_size) {
    const float* hidden = (const float*)d_in[0];
    const float* norm_w = (const float*)d_in[1];
    const float* in_proj_w = (const float*)d_in[2];
    const float* conv_w = (const float*)d_in[3];
    const float* conv_b = (const float*)d_in[4];
    const float* x_proj_w = (const float*)d_in[5];
    const float* dt_proj_w = (const float*)d_in[6];
    const float* dt_proj_b = (const float*)d_in[7];
    const float* A_log = (const float*)d_in[8];
    const float* D_skip = (const float*)d_in[9];
    const float* out_proj_w = (const float*)d_in[10];
    float* out = (float*)d_out;

    float *p_xnorm, *p_xz, *p_xconv, *p_dbl, *p_dblp, *p_dt, *p_y;
    float *p_w_in, *p_w_x, *p_w_dt, *p_w_out;
    cudaGetSymbolAddress((void**)&p_xnorm, g_xnorm);
    cudaGetSymbolAddress((void**)&p_xz, g_xz);
    cudaGetSymbolAddress((void**)&p_xconv, g_xconv);
    cudaGetSymbolAddress((void**)&p_dbl, g_dbl);
    cudaGetSymbolAddress((void**)&p_dblp, g_dblp);
    cudaGetSymbolAddress((void**)&p_dt, g_dt);
    cudaGetSymbolAddress((void**)&p_y, g_y);
    cudaGetSymbolAddress((void**)&p_w_in, g_w_in);
    cudaGetSymbolAddress((void**)&p_w_x, g_w_x);
    cudaGetSymbolAddress((void**)&p_w_dt, g_w_dt);
    cudaGetSymbolAddress((void**)&p_w_out, g_w_out);

    cudaFuncSetAttribute(gemm_tf32<1>, cudaFuncAttributeMaxDynamicSharedMemorySize, GSMEM);
    cudaFuncSetAttribute(gemm_tf32<0>, cudaFuncAttributeMaxDynamicSharedMemorySize, GSMEM);

    const int M = MTOT;

    // 0a. big weights -> tf32 permuted  (launch 1)
    {
        const int total = (NWI + NWO) / 8;
        cvt_weights_big<<<(total + 255) / 256, 256>>>((const float4*)in_proj_w,
                                                      (const float4*)out_proj_w);
    }
    // 0b. small weights (launch 2)
    {
        const int total = NWX / 8 + NWDT / 4;
        cvt_weights_small<<<(total + 255) / 256, 256>>>((const float4*)x_proj_w,
                                                        (const float4*)dt_proj_w);
    }

    // 1. RMSNorm (launch 3)
    rmsnorm_kernel<<<M, 128>>>(hidden, norm_w);

    // 2. in_proj (launch 4 — ncu capture window)
    {
        dim3 grid(2 * DIN / 128, M / 128, 1);
        gemm_tf32<1><<<grid, 256, GSMEM>>>(p_xnorm, DD, p_w_in, DD,
                                           p_xz, 2 * DIN, 0, DD, 2 * DIN, nullptr, 0);
    }

    // 3. conv + silu
    {
        const int total = (MTOT / 4) * (DIN / 8);
        conv_silu_kernel<<<(total + 255) / 256, 256>>>(conv_w, conv_b);
    }

    // 4. x_proj split-K
    {
        dim3 grid(1, M / 128, SPLITK);
        gemm_tf32<1><<<grid, 256, GSMEM>>>(p_xconv, DIN, p_w_x, DIN,
                                           p_dblp, DBLW, (size_t)MTOT * DBLW,
                                           DIN / SPLITK, DBLW, nullptr, 0);
        reduce_dbl<<<(MTOT * DBLW + 255) / 256, 256>>>();
    }

    // 5. dt_proj + bias + softplus (plain layout)
    {
        dim3 grid(DIN / 128, M / 128, 1);
        gemm_tf32<0><<<grid, 256, GSMEM>>>(p_dbl, DBLW, p_w_dt, RR,
                                           p_dt, DIN, 0, RR, DIN, dt_proj_b, 1);
    }

    // 6. selective scan
    {
        dim3 grid1(DIN / 128, SEG, BB);
        scan_pass1<<<grid1, 128>>>(A_log);
        scan_pass2<<<(BB * DIN + 255) / 256, 256>>>();
        scan_pass3<<<grid1, 128>>>(A_log, D_skip);
    }

    // 7. out_proj
    {
        dim3 grid(DD / 128, M / 128, 1);
        gemm_tf32<1><<<grid, 256, GSMEM>>>(p_y, DIN, p_w_out, DIN,
                                           out, DD, 0, DIN, DD, nullptr, 0);
    }
}

// round 11
// speedup vs baseline: 1.6848x; 1.6848x over previous
#include <cuda_runtime.h>
#include <cuda_fp16.h>
#include <math.h>
#include <stdint.h>

#define BB 4
#define LL 2048
#define DD 1024
#define DIN 1024
#define NS 8
#define RR 64
#define DBLW 80
#define SEG 32
#define SEGL (LL/SEG)     // 64
#define MTOT (BB*LL)
#define SPLITK 4

// ---------------- scratch ----------------
__device__ __half g_xnorm[MTOT*DD];
__device__ float  g_xz[MTOT*2*DIN];
__device__ __half g_xconv[MTOT*DIN];
__device__ float  g_dbl[MTOT*DBLW];      // fp32 for scan
__device__ __half g_dblh[MTOT*DBLW];     // fp16 for dt GEMM
__device__ float  g_dblp[SPLITK*MTOT*DBLW];
__device__ float  g_dt[MTOT*DIN];
__device__ __half g_y[MTOT*DIN];
__device__ float  g_segA[BB*SEG*NS*DIN];
__device__ float  g_segB[BB*SEG*NS*DIN];
__device__ float  g_hin[BB*SEG*NS*DIN];
__device__ __half g_w_in[2*DIN*DD];
__device__ __half g_w_x[DBLW*DIN];
__device__ __half g_w_dt[DIN*RR];
__device__ __half g_w_out[DD*DIN];

// ---------------- helpers ----------------
__device__ __forceinline__ uint32_t pack_h2(float a, float b) {
    __half2 h = __floats2half2_rn(a, b);
    return *reinterpret_cast<uint32_t*>(&h);
}

__device__ __forceinline__ void mma_f16(float c[4], const uint32_t a[4], const uint32_t b[2]) {
    asm volatile(
        "mma.sync.aligned.m16n8k16.row.col.f32.f16.f16.f32 "
        "{%0,%1,%2,%3}, {%4,%5,%6,%7}, {%8,%9}, {%0,%1,%2,%3};"
        : "+f"(c[0]), "+f"(c[1]), "+f"(c[2]), "+f"(c[3])
        : "r"(a[0]), "r"(a[1]), "r"(a[2]), "r"(a[3]), "r"(b[0]), "r"(b[1]));
}

__device__ __forceinline__ void cp16(uint32_t dst, const void* src, bool v) {
    int sz = v ? 16 : 0;
    asm volatile("cp.async.cg.shared.global [%0], [%1], 16, %2;\n"
                 :: "r"(dst), "l"(src), "r"(sz));
}

// ---------------- weight convert (fp32 -> fp16) ----------------
#define NWI (2*DIN*DD)
#define NWX (DBLW*DIN)
#define NWDT (DIN*RR)
#define NWO (DD*DIN)

__global__ __launch_bounds__(256) void cvt_weights_big(const float4* __restrict__ iw,
                                                       const float4* __restrict__ ow) {
    int i = blockIdx.x * 256 + threadIdx.x;   // 8 floats per thread
    const float4* src;
    uint4* dst;
    if (i < NWI/8) { src = iw + 2*i; dst = (uint4*)g_w_in + i; }
    else if ((i -= NWI/8) < NWO/8) { src = ow + 2*i; dst = (uint4*)g_w_out + i; }
    else return;
    const float4 a = src[0], b = src[1];
    uint4 v;
    v.x = pack_h2(a.x, a.y); v.y = pack_h2(a.z, a.w);
    v.z = pack_h2(b.x, b.y); v.w = pack_h2(b.z, b.w);
    *dst = v;
}

__global__ __launch_bounds__(256) void cvt_weights_small(const float4* __restrict__ xw,
                                                         const float4* __restrict__ dw) {
    int i = blockIdx.x * 256 + threadIdx.x;
    const float4* src;
    uint4* dst;
    if (i < NWX/8) { src = xw + 2*i; dst = (uint4*)g_w_x + i; }
    else if ((i -= NWX/8) < NWDT/8) { src = dw + 2*i; dst = (uint4*)g_w_dt + i; }
    else return;
    const float4 a = src[0], b = src[1];
    uint4 v;
    v.x = pack_h2(a.x, a.y); v.y = pack_h2(a.z, a.w);
    v.z = pack_h2(b.x, b.y); v.w = pack_h2(b.z, b.w);
    *dst = v;
}

// ---------------- RMSNorm (fp16 output) ----------------
__global__ __launch_bounds__(128) void rmsnorm_kernel(const float* __restrict__ x,
                                                      const float* __restrict__ w) {
    const int row = blockIdx.x;
    const int t = threadIdx.x;                 // 128 threads x 8 floats
    const float4* xr4 = (const float4*)(x + (size_t)row * DD);
    const float4 v0 = xr4[2*t], v1 = xr4[2*t + 1];
    float ss = v0.x*v0.x + v0.y*v0.y + v0.z*v0.z + v0.w*v0.w
             + v1.x*v1.x + v1.y*v1.y + v1.z*v1.z + v1.w*v1.w;
#pragma unroll
    for (int o = 16; o > 0; o >>= 1) ss += __shfl_xor_sync(0xffffffffu, ss, o);
    __shared__ float red[4];
    if ((t & 31) == 0) red[t >> 5] = ss;
    __syncthreads();
    const float tot = red[0] + red[1] + red[2] + red[3];
    const float sc = rsqrtf(tot * (1.f / DD) + 1e-5f);
    const float4 w0 = ((const float4*)w)[2*t], w1 = ((const float4*)w)[2*t + 1];
    uint4 v;
    v.x = pack_h2(v0.x * sc * w0.x, v0.y * sc * w0.y);
    v.y = pack_h2(v0.z * sc * w0.z, v0.w * sc * w0.w);
    v.z = pack_h2(v1.x * sc * w1.x, v1.y * sc * w1.y);
    v.w = pack_h2(v1.z * sc * w1.z, v1.w * sc * w1.w);
    ((uint4*)(g_xnorm + (size_t)row * DD))[t] = v;
}

// ---------------- FP16 GEMM: BM=BN=128, BK=64 halves, 256 thr, 8 warps 32x64 ----------------
// smem row stride 36 words (72 halves): conflict-free 4g+tg bank pattern.
#define GSTAGES 3
#define SWORDS (128*36)
#define STGB (SWORDS*4)          // 18432 B
#define GSMEM (2*GSTAGES*STGB)   // 110592 B

__global__ __launch_bounds__(256, 2) void gemm_f16(
    const __half* __restrict__ A, int lda,
    const __half* __restrict__ W, int ldw,
    float* __restrict__ C, int ldc, size_t cstride,
    int K, int E,
    const float* __restrict__ bias, int epi)
{
    extern __shared__ uint32_t smw[];
    uint32_t* sA = smw;
    uint32_t* sB = smw + GSTAGES * SWORDS;

    const int tid = threadIdx.x;
    const int lane = tid & 31;
    const int wid = tid >> 5;
    const int m0 = blockIdx.y * 128;
    const int e0 = blockIdx.x * 128;
    const int z = blockIdx.z;
    const int mw = (wid & 3) * 32;
    const int nw = (wid >> 2) * 64;

    const int prow = tid >> 3;        // 0..31
    const int pk = (tid & 7) * 8;     // half index 0..56

    const __half* aP[4];
    const __half* wP[4];
    bool wv[4];
    uint32_t dAo[4], dBo[4];
    const uint32_t sAu = (uint32_t)__cvta_generic_to_shared(sA);
    const uint32_t sBu = (uint32_t)__cvta_generic_to_shared(sB);
#pragma unroll
    for (int c = 0; c < 4; c++) {
        const int r = prow + 32 * c;
        aP[c] = A + (size_t)(m0 + r) * lda + (size_t)z * K + pk;
        const int er = e0 + r;
        wv[c] = er < E;
        wP[c] = W + (size_t)(wv[c] ? er : 0) * ldw + (size_t)z * K + pk;
        dAo[c] = sAu + (r * 36 + (tid & 7) * 4) * 4;
        dBo[c] = sBu + (r * 36 + (tid & 7) * 4) * 4;
    }

    float acc[2][8][4];
#pragma unroll
    for (int i = 0; i < 2; i++)
#pragma unroll
        for (int j = 0; j < 8; j++)
#pragma unroll
            for (int l = 0; l < 4; l++) acc[i][j][l] = 0.f;

    const int T = K / 64;

#pragma unroll
    for (int p = 0; p < GSTAGES - 1; p++) {
        if (p < T) {
            const int ko = p * 64;
#pragma unroll
            for (int c = 0; c < 4; c++) {
                cp16(dAo[c] + p * STGB, aP[c] + ko, true);
                cp16(dBo[c] + p * STGB, wP[c] + ko, wv[c]);
            }
        }
        asm volatile("cp.async.commit_group;\n");
    }

    const int g = lane >> 2;
    const int tg = lane & 3;

    for (int t = 0; t < T; t++) {
        asm volatile("cp.async.wait_group 1;\n");
        __syncthreads();

        // prefetch next stage before compute
        {
            const int tn = t + GSTAGES - 1;
            if (tn < T) {
                const int ko = tn * 64;
                const int so = tn % GSTAGES;
#pragma unroll
                for (int c = 0; c < 4; c++) {
                    cp16(dAo[c] + so * STGB, aP[c] + ko, true);
                    cp16(dBo[c] + so * STGB, wP[c] + ko, wv[c]);
                }
            }
            asm volatile("cp.async.commit_group;\n");
        }

        const int stg = t % GSTAGES;
        const uint32_t* At = sA + stg * SWORDS;
        const uint32_t* Bt = sB + stg * SWORDS;

#pragma unroll
        for (int ks = 0; ks < 4; ks++) {          // 4 x k16 per 64-half tile
            const int kk = ks * 8;                // word offset
            uint32_t af[2][4];
            uint32_t bf[8][2];
#pragma unroll
            for (int mt = 0; mt < 2; mt++) {
                const int mb = mw + mt * 16 + g;
                af[mt][0] = At[mb * 36 + kk + tg];
                af[mt][1] = At[(mb + 8) * 36 + kk + tg];
                af[mt][2] = At[mb * 36 + kk + 4 + tg];
                af[mt][3] = At[(mb + 8) * 36 + kk + 4 + tg];
            }
#pragma unroll
            for (int nt = 0; nt < 8; nt++) {
                const int nb = nw + nt * 8 + g;
                bf[nt][0] = Bt[nb * 36 + kk + tg];
                bf[nt][1] = Bt[nb * 36 + kk + 4 + tg];
            }
#pragma unroll
            for (int mt = 0; mt < 2; mt++)
#pragma unroll
                for (int nt = 0; nt < 8; nt++)
                    mma_f16(acc[mt][nt], af[mt], bf[nt]);
        }
    }

    // epilogue (fp32, float2 stores)
    float* Cz = C + (size_t)z * cstride;
#pragma unroll
    for (int mt = 0; mt < 2; mt++) {
        const int r0 = m0 + mw + mt * 16 + g;
        const int r1 = r0 + 8;
#pragma unroll
        for (int nt = 0; nt < 8; nt++) {
            const int c0 = e0 + nw + nt * 8 + tg * 2;
            if (c0 < E) {
                float va0 = acc[mt][nt][0], va1 = acc[mt][nt][1];
                float vb0 = acc[mt][nt][2], vb1 = acc[mt][nt][3];
                if (epi == 1) {
                    const float b0 = bias[c0], b1 = bias[c0 + 1];
                    va0 += b0; va0 = fmaxf(va0, 0.f) + log1pf(__expf(-fabsf(va0)));
                    va1 += b1; va1 = fmaxf(va1, 0.f) + log1pf(__expf(-fabsf(va1)));
                    vb0 += b0; vb0 = fmaxf(vb0, 0.f) + log1pf(__expf(-fabsf(vb0)));
                    vb1 += b1; vb1 = fmaxf(vb1, 0.f) + log1pf(__expf(-fabsf(vb1)));
                }
                *(float2*)(Cz + (size_t)r0 * ldc + c0) = make_float2(va0, va1);
                *(float2*)(Cz + (size_t)r1 * ldc + c0) = make_float2(vb0, vb1);
            }
        }
    }
}

// ---------------- split-K reduce for x_proj ----------------
__global__ __launch_bounds__(256) void reduce_dbl() {
    const int idx = blockIdx.x * 256 + threadIdx.x;
    if (idx >= MTOT * DBLW) return;
    float s = 0.f;
#pragma unroll
    for (int p = 0; p < SPLITK; p++) s += g_dblp[(size_t)p * MTOT * DBLW + idx];
    g_dbl[idx] = s;
    g_dblh[idx] = __float2half_rn(s);
}

// ---------------- conv+silu: 4 rows x 8 ch, fp16 output ----------------
__global__ __launch_bounds__(256) void conv_silu_kernel(const float* __restrict__ conv_w,
                                                        const float* __restrict__ conv_b) {
    const int t = blockIdx.x * 256 + threadIdx.x;
    const int nd8 = DIN / 8;                 // 128
    const int d0 = (t % nd8) * 8;
    const int m0 = (t / nd8) * 4;
    if (m0 >= MTOT) return;
    const int l0 = m0 % LL;
    const int b = m0 / LL;

    float4 xa[7], xb[7];
#pragma unroll
    for (int j = 0; j < 7; j++) {
        const int ls = l0 - 3 + j;
        if (ls >= 0) {
            const float* base = g_xz + ((size_t)(b * LL + ls)) * (2 * DIN) + d0;
            xa[j] = *(const float4*)base;
            xb[j] = *(const float4*)(base + 4);
        } else {
            xa[j] = make_float4(0.f, 0.f, 0.f, 0.f);
            xb[j] = xa[j];
        }
    }
    float4 wr[8];
#pragma unroll
    for (int c = 0; c < 8; c++) wr[c] = *(const float4*)(conv_w + (d0 + c) * 4);
    const float4 ba = *(const float4*)(conv_b + d0);
    const float4 bb = *(const float4*)(conv_b + d0 + 4);

#pragma unroll
    for (int i = 0; i < 4; i++) {
        float o[8];
        o[0] = ba.x; o[1] = ba.y; o[2] = ba.z; o[3] = ba.w;
        o[4] = bb.x; o[5] = bb.y; o[6] = bb.z; o[7] = bb.w;
#pragma unroll
        for (int j = 0; j < 4; j++) {
            const float4 va = xa[i + j];
            const float4 vb = xb[i + j];
            o[0] += ((const float*)&wr[0])[j] * va.x;
            o[1] += ((const float*)&wr[1])[j] * va.y;
            o[2] += ((const float*)&wr[2])[j] * va.z;
            o[3] += ((const float*)&wr[3])[j] * va.w;
            o[4] += ((const float*)&wr[4])[j] * vb.x;
            o[5] += ((const float*)&wr[5])[j] * vb.y;
            o[6] += ((const float*)&wr[6])[j] * vb.z;
            o[7] += ((const float*)&wr[7])[j] * vb.w;
        }
#pragma unroll
        for (int c = 0; c < 8; c++) o[c] = o[c] / (1.f + __expf(-o[c]));
        uint4 v;
        v.x = pack_h2(o[0], o[1]); v.y = pack_h2(o[2], o[3]);
        v.z = pack_h2(o[4], o[5]); v.w = pack_h2(o[6], o[7]);
        *(uint4*)(g_xconv + ((size_t)(m0 + i)) * DIN + d0) = v;
    }
}

// ---------------- chunked selective scan (SEG=32) ----------------
__global__ __launch_bounds__(128) void scan_pass1(const float* __restrict__ A_log) {
    const int b = blockIdx.z;
    const int s = blockIdx.y;
    const int d = blockIdx.x * 128 + threadIdx.x;
    const int tid = threadIdx.x;
    const int l0 = s * SEGL;

    float A[NS];
#pragma unroll
    for (int n = 0; n < NS; n++) A[n] = -__expf(A_log[d * NS + n]);

    float p[NS], h[NS];
#pragma unroll
    for (int n = 0; n < NS; n++) { p[n] = 1.f; h[n] = 0.f; }

    __shared__ float sB[SEGL][NS];
    for (int i = tid; i < SEGL * NS; i += 128) {
        const int ll = i >> 3;
        const int n = i & 7;
        sB[ll][n] = g_dbl[((size_t)(b * LL + l0 + ll)) * DBLW + RR + n];
    }
    __syncthreads();

    for (int j = 0; j < SEGL; j++) {
        const size_t rowb = ((size_t)(b * LL + l0 + j)) * DIN;
        const float dtv = g_dt[rowb + d];
        const float xv = __half2float(g_xconv[rowb + d]);
        const float dtx = dtv * xv;
#pragma unroll
        for (int n = 0; n < NS; n++) {
            const float da = __expf(dtv * A[n]);
            p[n] *= da;
            h[n] = da * h[n] + dtx * sB[j][n];
        }
    }
#pragma unroll
    for (int n = 0; n < NS; n++) {
        const size_t o = ((size_t)((b * SEG + s) * NS + n)) * DIN + d;
        g_segA[o] = p[n];
        g_segB[o] = h[n];
    }
}

__global__ __launch_bounds__(256) void scan_pass2() {
    const int gidx = blockIdx.x * 256 + threadIdx.x;
    if (gidx >= BB * DIN) return;
    const int b = gidx / DIN;
    const int d = gidx % DIN;
    float h[NS];
#pragma unroll
    for (int n = 0; n < NS; n++) h[n] = 0.f;
    for (int s = 0; s < SEG; s++) {
#pragma unroll
        for (int n = 0; n < NS; n++) {
            const size_t o = ((size_t)((b * SEG + s) * NS + n)) * DIN + d;
            g_hin[o] = h[n];
            h[n] = g_segA[o] * h[n] + g_segB[o];
        }
    }
}

__global__ __launch_bounds__(128) void scan_pass3(const float* __restrict__ A_log,
                                                  const float* __restrict__ D_skip) {
    const int b = blockIdx.z;
    const int s = blockIdx.y;
    const int d = blockIdx.x * 128 + threadIdx.x;
    const int tid = threadIdx.x;
    const int l0 = s * SEGL;

    float A[NS];
#pragma unroll
    for (int n = 0; n < NS; n++) A[n] = -__expf(A_log[d * NS + n]);
    const float dsk = D_skip[d];

    float h[NS];
#pragma unroll
    for (int n = 0; n < NS; n++)
        h[n] = g_hin[((size_t)((b * SEG + s) * NS + n)) * DIN + d];

    __shared__ float sB[SEGL][NS];
    __shared__ float sC[SEGL][NS];
    for (int i = tid; i < SEGL * NS * 2; i += 128) {
        const int ll = i >> 4;
        const int c = i & 15;
        const float v = g_dbl[((size_t)(b * LL + l0 + ll)) * DBLW + RR + c];
        if (c < NS) sB[ll][c] = v;
        else        sC[ll][c - NS] = v;
    }
    __syncthreads();

    for (int j = 0; j < SEGL; j++) {
        const size_t rowb = ((size_t)(b * LL + l0 + j)) * DIN;
        const float dtv = g_dt[rowb + d];
        const float xv = __half2float(g_xconv[rowb + d]);
        const float dtx = dtv * xv;
        float yv = 0.f;
#pragma unroll
        for (int n = 0; n < NS; n++) {
            const float da = __expf(dtv * A[n]);
            h[n] = da * h[n] + dtx * sB[j][n];
            yv += h[n] * sC[j][n];
        }
        const float z = g_xz[((size_t)(b * LL + l0 + j)) * (2 * DIN) + DIN + d];
        const float sz = z / (1.f + __expf(-z));
        g_y[rowb + d] = __float2half_rn((yv + dsk * xv) * sz);
    }
}

// ---------------- launch ----------------
extern "C" void kernel_launch(void* const* d_in, const int* in_sizes, int n_in,
                              void* d_out, int out_size) {
    const float* hidden = (const float*)d_in[0];
    const float* norm_w = (const float*)d_in[1];
    const float* in_proj_w = (const float*)d_in[2];
    const float* conv_w = (const float*)d_in[3];
    const float* conv_b = (const float*)d_in[4];
    const float* x_proj_w = (const float*)d_in[5];
    const float* dt_proj_w = (const float*)d_in[6];
    const float* dt_proj_b = (const float*)d_in[7];
    const float* A_log = (const float*)d_in[8];
    const float* D_skip = (const float*)d_in[9];
    const float* out_proj_w = (const float*)d_in[10];
    float* out = (float*)d_out;

    __half *p_xnorm, *p_xconv, *p_dblh, *p_y;
    __half *p_w_in, *p_w_x, *p_w_dt, *p_w_out;
    float *p_dblp;
    cudaGetSymbolAddress((void**)&p_xnorm, g_xnorm);
    cudaGetSymbolAddress((void**)&p_xconv, g_xconv);
    cudaGetSymbolAddress((void**)&p_dblh, g_dblh);
    cudaGetSymbolAddress((void**)&p_y, g_y);
    cudaGetSymbolAddress((void**)&p_dblp, g_dblp);
    cudaGetSymbolAddress((void**)&p_w_in, g_w_in);
    cudaGetSymbolAddress((void**)&p_w_x, g_w_x);
    cudaGetSymbolAddress((void**)&p_w_dt, g_w_dt);
    cudaGetSymbolAddress((void**)&p_w_out, g_w_out);
    float *p_xz, *p_dt;
    cudaGetSymbolAddress((void**)&p_xz, g_xz);
    cudaGetSymbolAddress((void**)&p_dt, g_dt);

    cudaFuncSetAttribute(gemm_f16, cudaFuncAttributeMaxDynamicSharedMemorySize, GSMEM);

    const int M = MTOT;

    // 0a. big weights -> fp16 (launch 1)
    {
        const int total = (NWI + NWO) / 8;
        cvt_weights_big<<<(total + 255) / 256, 256>>>((const float4*)in_proj_w,
                                                      (const float4*)out_proj_w);
    }
    // 0b. small weights (launch 2)
    {
        const int total = (NWX + NWDT) / 8;
        cvt_weights_small<<<(total + 255) / 256, 256>>>((const float4*)x_proj_w,
                                                        (const float4*)dt_proj_w);
    }

    // 1. RMSNorm (launch 3)
    rmsnorm_kernel<<<M, 128>>>(hidden, norm_w);

    // 2. in_proj (launch 4 — ncu capture window)
    {
        dim3 grid(2 * DIN / 128, M / 128, 1);
        gemm_f16<<<grid, 256, GSMEM>>>(p_xnorm, DD, p_w_in, DD,
                                       p_xz, 2 * DIN, 0, DD, 2 * DIN, nullptr, 0);
    }

    // 3. conv + silu
    {
        const int total = (MTOT / 4) * (DIN / 8);
        conv_silu_kernel<<<(total + 255) / 256, 256>>>(conv_w, conv_b);
    }

    // 4. x_proj split-K (K=256 per split)
    {
        dim3 grid(1, M / 128, SPLITK);
        gemm_f16<<<grid, 256, GSMEM>>>(p_xconv, DIN, p_w_x, DIN,
                                       p_dblp, DBLW, (size_t)MTOT * DBLW,
                                       DIN / SPLITK, DBLW, nullptr, 0);
        reduce_dbl<<<(MTOT * DBLW + 255) / 256, 256>>>();
    }

    // 5. dt_proj + bias + softplus (K=64, single tile)
    {
        dim3 grid(DIN / 128, M / 128, 1);
        gemm_f16<<<grid, 256, GSMEM>>>(p_dblh, DBLW, p_w_dt, RR,
                                       p_dt, DIN, 0, RR, DIN, dt_proj_b, 1);
    }

    // 6. selective scan
    {
        dim3 grid1(DIN / 128, SEG, BB);
        scan_pass1<<<grid1, 128>>>(A_log);
        scan_pass2<<<(BB * DIN + 255) / 256, 256>>>();
        scan_pass3<<<grid1, 128>>>(A_log, D_skip);
    }

    // 7. out_proj
    {
        dim3 grid(DD / 128, M / 128, 1);
        gemm_f16<<<grid, 256, GSMEM>>>(p_y, DIN, p_w_out, DIN,
                                       out, DD, 0, DIN, DD, nullptr, 0);
    }
}

// round 12
// speedup vs baseline: 1.7591x; 1.0441x over previous
#include <cuda_runtime.h>
#include <cuda_fp16.h>
#include <math.h>
#include <stdint.h>

#define BB 4
#define LL 2048
#define DD 1024
#define DIN 1024
#define NS 8
#define RR 64
#define DBLW 80
#define SEG 32
#define SEGL (LL/SEG)     // 64
#define MTOT (BB*LL)
#define SPLITK 4

// ---------------- scratch ----------------
__device__ __half g_xnorm[MTOT*DD];
__device__ float  g_xz[MTOT*2*DIN];
__device__ __half g_xconv[MTOT*DIN];
__device__ float  g_dbl[MTOT*DBLW];
__device__ __half g_dblh[MTOT*DBLW];
__device__ float  g_dblp[SPLITK*MTOT*DBLW];
__device__ float  g_dt[MTOT*DIN];
__device__ __half g_y[MTOT*DIN];
__device__ float  g_segA[BB*SEG*NS*DIN];
__device__ float  g_segB[BB*SEG*NS*DIN];
__device__ float  g_hin[BB*SEG*NS*DIN];
__device__ __half g_w_in[2*DIN*DD];
__device__ __half g_w_x[DBLW*DIN];
__device__ __half g_w_dt[DIN*RR];
__device__ __half g_w_out[DD*DIN];

// ---------------- helpers ----------------
__device__ __forceinline__ uint32_t pack_h2(float a, float b) {
    __half2 h = __floats2half2_rn(a, b);
    return *reinterpret_cast<uint32_t*>(&h);
}

__device__ __forceinline__ void mma_f16(float c[4], const uint32_t a[4], const uint32_t b[2]) {
    asm volatile(
        "mma.sync.aligned.m16n8k16.row.col.f32.f16.f16.f32 "
        "{%0,%1,%2,%3}, {%4,%5,%6,%7}, {%8,%9}, {%0,%1,%2,%3};"
        : "+f"(c[0]), "+f"(c[1]), "+f"(c[2]), "+f"(c[3])
        : "r"(a[0]), "r"(a[1]), "r"(a[2]), "r"(a[3]), "r"(b[0]), "r"(b[1]));
}

__device__ __forceinline__ void ldsm4(uint32_t r[4], uint32_t addr) {
    asm volatile("ldmatrix.sync.aligned.m8n8.x4.shared.b16 {%0,%1,%2,%3}, [%4];"
                 : "=r"(r[0]), "=r"(r[1]), "=r"(r[2]), "=r"(r[3]) : "r"(addr));
}

__device__ __forceinline__ void cp16(uint32_t dst, const void* src, bool v) {
    int sz = v ? 16 : 0;
    asm volatile("cp.async.cg.shared.global [%0], [%1], 16, %2;\n"
                 :: "r"(dst), "l"(src), "r"(sz));
}

// ---------------- weight convert (fp32 -> fp16) ----------------
#define NWI (2*DIN*DD)
#define NWX (DBLW*DIN)
#define NWDT (DIN*RR)
#define NWO (DD*DIN)

__global__ __launch_bounds__(256) void cvt_weights_big(const float4* __restrict__ iw,
                                                       const float4* __restrict__ ow) {
    int i = blockIdx.x * 256 + threadIdx.x;
    const float4* src;
    uint4* dst;
    if (i < NWI/8) { src = iw + 2*i; dst = (uint4*)g_w_in + i; }
    else if ((i -= NWI/8) < NWO/8) { src = ow + 2*i; dst = (uint4*)g_w_out + i; }
    else return;
    const float4 a = src[0], b = src[1];
    uint4 v;
    v.x = pack_h2(a.x, a.y); v.y = pack_h2(a.z, a.w);
    v.z = pack_h2(b.x, b.y); v.w = pack_h2(b.z, b.w);
    *dst = v;
}

__global__ __launch_bounds__(256) void cvt_weights_small(const float4* __restrict__ xw,
                                                         const float4* __restrict__ dw) {
    int i = blockIdx.x * 256 + threadIdx.x;
    const float4* src;
    uint4* dst;
    if (i < NWX/8) { src = xw + 2*i; dst = (uint4*)g_w_x + i; }
    else if ((i -= NWX/8) < NWDT/8) { src = dw + 2*i; dst = (uint4*)g_w_dt + i; }
    else return;
    const float4 a = src[0], b = src[1];
    uint4 v;
    v.x = pack_h2(a.x, a.y); v.y = pack_h2(a.z, a.w);
    v.z = pack_h2(b.x, b.y); v.w = pack_h2(b.z, b.w);
    *dst = v;
}

// ---------------- RMSNorm (fp16 output) ----------------
__global__ __launch_bounds__(128) void rmsnorm_kernel(const float* __restrict__ x,
                                                      const float* __restrict__ w) {
    const int row = blockIdx.x;
    const int t = threadIdx.x;
    const float4* xr4 = (const float4*)(x + (size_t)row * DD);
    const float4 v0 = xr4[2*t], v1 = xr4[2*t + 1];
    float ss = v0.x*v0.x + v0.y*v0.y + v0.z*v0.z + v0.w*v0.w
             + v1.x*v1.x + v1.y*v1.y + v1.z*v1.z + v1.w*v1.w;
#pragma unroll
    for (int o = 16; o > 0; o >>= 1) ss += __shfl_xor_sync(0xffffffffu, ss, o);
    __shared__ float red[4];
    if ((t & 31) == 0) red[t >> 5] = ss;
    __syncthreads();
    const float tot = red[0] + red[1] + red[2] + red[3];
    const float sc = rsqrtf(tot * (1.f / DD) + 1e-5f);
    const float4 w0 = ((const float4*)w)[2*t], w1 = ((const float4*)w)[2*t + 1];
    uint4 v;
    v.x = pack_h2(v0.x * sc * w0.x, v0.y * sc * w0.y);
    v.y = pack_h2(v0.z * sc * w0.z, v0.w * sc * w0.w);
    v.z = pack_h2(v1.x * sc * w1.x, v1.y * sc * w1.y);
    v.w = pack_h2(v1.z * sc * w1.z, v1.w * sc * w1.w);
    ((uint4*)(g_xnorm + (size_t)row * DD))[t] = v;
}

// ---------------- FP16 GEMM + ldmatrix: BM=BN=128, BK=64h, 256 thr, 8 warps 32x64 ----------------
#define GSTAGES 3
#define SWORDS (128*36)
#define STGB (SWORDS*4)          // 18432 B
#define GSMEM (2*GSTAGES*STGB)   // 110592 B

__global__ __launch_bounds__(256, 2) void gemm_f16(
    const __half* __restrict__ A, int lda,
    const __half* __restrict__ W, int ldw,
    float* __restrict__ C, int ldc, size_t cstride,
    int K, int E,
    const float* __restrict__ bias, int epi)
{
    extern __shared__ uint32_t smw[];
    uint32_t* sA = smw;
    uint32_t* sB = smw + GSTAGES * SWORDS;

    const int tid = threadIdx.x;
    const int lane = tid & 31;
    const int wid = tid >> 5;
    const int m0 = blockIdx.y * 128;
    const int e0 = blockIdx.x * 128;
    const int z = blockIdx.z;
    const int mw = (wid & 3) * 32;
    const int nw = (wid >> 2) * 64;

    const int prow = tid >> 3;
    const int pk = (tid & 7) * 8;

    const __half* aP[4];
    const __half* wP[4];
    bool wv[4];
    uint32_t dAo[4], dBo[4];
    const uint32_t sAu = (uint32_t)__cvta_generic_to_shared(sA);
    const uint32_t sBu = (uint32_t)__cvta_generic_to_shared(sB);
#pragma unroll
    for (int c = 0; c < 4; c++) {
        const int r = prow + 32 * c;
        aP[c] = A + (size_t)(m0 + r) * lda + (size_t)z * K + pk;
        const int er = e0 + r;
        wv[c] = er < E;
        wP[c] = W + (size_t)(wv[c] ? er : 0) * ldw + (size_t)z * K + pk;
        dAo[c] = sAu + (r * 36 + (tid & 7) * 4) * 4;
        dBo[c] = sBu + (r * 36 + (tid & 7) * 4) * 4;
    }

    // ldmatrix lane-address bases (word offsets within a stage)
    const int quad = lane >> 3;        // 0..3
    const int qrow = lane & 7;         // 0..7
    // A x4: quad0=(mlo,klo) quad1=(mhi,klo) quad2=(mlo,khi) quad3=(mhi,khi)
    uint32_t aoff[2];
#pragma unroll
    for (int mt = 0; mt < 2; mt++) {
        const int row = mw + mt * 16 + (quad & 1) * 8 + qrow;
        aoff[mt] = (uint32_t)(row * 36 + (quad >> 1) * 4);
    }
    // B x4 per n16 pair: quad0=(nlo,klo) quad1=(nlo,khi) quad2=(nhi,klo) quad3=(nhi,khi)
    uint32_t boff[4];
#pragma unroll
    for (int np = 0; np < 4; np++) {
        const int row = nw + np * 16 + (quad >> 1) * 8 + qrow;
        boff[np] = (uint32_t)(row * 36 + (quad & 1) * 4);
    }

    float acc[2][8][4];
#pragma unroll
    for (int i = 0; i < 2; i++)
#pragma unroll
        for (int j = 0; j < 8; j++)
#pragma unroll
            for (int l = 0; l < 4; l++) acc[i][j][l] = 0.f;

    const int T = K / 64;

#pragma unroll
    for (int p = 0; p < GSTAGES - 1; p++) {
        if (p < T) {
            const int ko = p * 64;
#pragma unroll
            for (int c = 0; c < 4; c++) {
                cp16(dAo[c] + p * STGB, aP[c] + ko, true);
                cp16(dBo[c] + p * STGB, wP[c] + ko, wv[c]);
            }
        }
        asm volatile("cp.async.commit_group;\n");
    }

    for (int t = 0; t < T; t++) {
        asm volatile("cp.async.wait_group 1;\n");
        __syncthreads();

        // prefetch next stage before compute
        {
            const int tn = t + GSTAGES - 1;
            if (tn < T) {
                const int ko = tn * 64;
                const int so = tn % GSTAGES;
#pragma unroll
                for (int c = 0; c < 4; c++) {
                    cp16(dAo[c] + so * STGB, aP[c] + ko, true);
                    cp16(dBo[c] + so * STGB, wP[c] + ko, wv[c]);
                }
            }
            asm volatile("cp.async.commit_group;\n");
        }

        const int stg = t % GSTAGES;
        const uint32_t stgw = (uint32_t)(stg * SWORDS);
        const uint32_t aBase = sAu + stgw * 4;
        const uint32_t bBase = sBu + stgw * 4;

#pragma unroll
        for (int ks = 0; ks < 4; ks++) {
            const uint32_t kk4 = (uint32_t)(ks * 8) * 4;   // byte offset of k16 block
            uint32_t af[2][4];
            uint32_t bq[4][4];
#pragma unroll
            for (int mt = 0; mt < 2; mt++)
                ldsm4(af[mt], aBase + (aoff[mt] * 4) + kk4);
#pragma unroll
            for (int np = 0; np < 4; np++)
                ldsm4(bq[np], bBase + (boff[np] * 4) + kk4);

#pragma unroll
            for (int mt = 0; mt < 2; mt++)
#pragma unroll
                for (int np = 0; np < 4; np++) {
                    mma_f16(acc[mt][2*np],     af[mt], &bq[np][0]);   // n lo: b0=klo, b1=khi
                    mma_f16(acc[mt][2*np + 1], af[mt], &bq[np][2]);   // n hi
                }
        }
    }

    // epilogue (fp32, float2 stores)
    const int g = lane >> 2;
    const int tg = lane & 3;
    float* Cz = C + (size_t)z * cstride;
#pragma unroll
    for (int mt = 0; mt < 2; mt++) {
        const int r0 = m0 + mw + mt * 16 + g;
        const int r1 = r0 + 8;
#pragma unroll
        for (int nt = 0; nt < 8; nt++) {
            const int c0 = e0 + nw + nt * 8 + tg * 2;
            if (c0 < E) {
                float va0 = acc[mt][nt][0], va1 = acc[mt][nt][1];
                float vb0 = acc[mt][nt][2], vb1 = acc[mt][nt][3];
                if (epi == 1) {
                    const float b0 = bias[c0], b1 = bias[c0 + 1];
                    va0 += b0; va0 = fmaxf(va0, 0.f) + log1pf(__expf(-fabsf(va0)));
                    va1 += b1; va1 = fmaxf(va1, 0.f) + log1pf(__expf(-fabsf(va1)));
                    vb0 += b0; vb0 = fmaxf(vb0, 0.f) + log1pf(__expf(-fabsf(vb0)));
                    vb1 += b1; vb1 = fmaxf(vb1, 0.f) + log1pf(__expf(-fabsf(vb1)));
                }
                *(float2*)(Cz + (size_t)r0 * ldc + c0) = make_float2(va0, va1);
                *(float2*)(Cz + (size_t)r1 * ldc + c0) = make_float2(vb0, vb1);
            }
        }
    }
}

// ---------------- split-K reduce for x_proj ----------------
__global__ __launch_bounds__(256) void reduce_dbl() {
    const int idx = blockIdx.x * 256 + threadIdx.x;
    if (idx >= MTOT * DBLW) return;
    float s = 0.f;
#pragma unroll
    for (int p = 0; p < SPLITK; p++) s += g_dblp[(size_t)p * MTOT * DBLW + idx];
    g_dbl[idx] = s;
    g_dblh[idx] = __float2half_rn(s);
}

// ---------------- conv+silu: 4 rows x 8 ch, fp16 output ----------------
__global__ __launch_bounds__(256) void conv_silu_kernel(const float* __restrict__ conv_w,
                                                        const float* __restrict__ conv_b) {
    const int t = blockIdx.x * 256 + threadIdx.x;
    const int nd8 = DIN / 8;
    const int d0 = (t % nd8) * 8;
    const int m0 = (t / nd8) * 4;
    if (m0 >= MTOT) return;
    const int l0 = m0 % LL;
    const int b = m0 / LL;

    float4 xa[7], xb[7];
#pragma unroll
    for (int j = 0; j < 7; j++) {
        const int ls = l0 - 3 + j;
        if (ls >= 0) {
            const float* base = g_xz + ((size_t)(b * LL + ls)) * (2 * DIN) + d0;
            xa[j] = *(const float4*)base;
            xb[j] = *(const float4*)(base + 4);
        } else {
            xa[j] = make_float4(0.f, 0.f, 0.f, 0.f);
            xb[j] = xa[j];
        }
    }
    float4 wr[8];
#pragma unroll
    for (int c = 0; c < 8; c++) wr[c] = *(const float4*)(conv_w + (d0 + c) * 4);
    const float4 ba = *(const float4*)(conv_b + d0);
    const float4 bb = *(const float4*)(conv_b + d0 + 4);

#pragma unroll
    for (int i = 0; i < 4; i++) {
        float o[8];
        o[0] = ba.x; o[1] = ba.y; o[2] = ba.z; o[3] = ba.w;
        o[4] = bb.x; o[5] = bb.y; o[6] = bb.z; o[7] = bb.w;
#pragma unroll
        for (int j = 0; j < 4; j++) {
            const float4 va = xa[i + j];
            const float4 vb = xb[i + j];
            o[0] += ((const float*)&wr[0])[j] * va.x;
            o[1] += ((const float*)&wr[1])[j] * va.y;
            o[2] += ((const float*)&wr[2])[j] * va.z;
            o[3] += ((const float*)&wr[3])[j] * va.w;
            o[4] += ((const float*)&wr[4])[j] * vb.x;
            o[5] += ((const float*)&wr[5])[j] * vb.y;
            o[6] += ((const float*)&wr[6])[j] * vb.z;
            o[7] += ((const float*)&wr[7])[j] * vb.w;
        }
#pragma unroll
        for (int c = 0; c < 8; c++) o[c] = o[c] / (1.f + __expf(-o[c]));
        uint4 v;
        v.x = pack_h2(o[0], o[1]); v.y = pack_h2(o[2], o[3]);
        v.z = pack_h2(o[4], o[5]); v.w = pack_h2(o[6], o[7]);
        *(uint4*)(g_xconv + ((size_t)(m0 + i)) * DIN + d0) = v;
    }
}

// ---------------- chunked selective scan (SEG=32) ----------------
__global__ __launch_bounds__(128) void scan_pass1(const float* __restrict__ A_log) {
    const int b = blockIdx.z;
    const int s = blockIdx.y;
    const int d = blockIdx.x * 128 + threadIdx.x;
    const int tid = threadIdx.x;
    const int l0 = s * SEGL;

    float A[NS];
#pragma unroll
    for (int n = 0; n < NS; n++) A[n] = -__expf(A_log[d * NS + n]);

    float p[NS], h[NS];
#pragma unroll
    for (int n = 0; n < NS; n++) { p[n] = 1.f; h[n] = 0.f; }

    __shared__ float sB[SEGL][NS];
    for (int i = tid; i < SEGL * NS; i += 128) {
        const int ll = i >> 3;
        const int n = i & 7;
        sB[ll][n] = g_dbl[((size_t)(b * LL + l0 + ll)) * DBLW + RR + n];
    }
    __syncthreads();

    for (int j = 0; j < SEGL; j++) {
        const size_t rowb = ((size_t)(b * LL + l0 + j)) * DIN;
        const float dtv = g_dt[rowb + d];
        const float xv = __half2float(g_xconv[rowb + d]);
        const float dtx = dtv * xv;
#pragma unroll
        for (int n = 0; n < NS; n++) {
            const float da = __expf(dtv * A[n]);
            p[n] *= da;
            h[n] = da * h[n] + dtx * sB[j][n];
        }
    }
#pragma unroll
    for (int n = 0; n < NS; n++) {
        const size_t o = ((size_t)((b * SEG + s) * NS + n)) * DIN + d;
        g_segA[o] = p[n];
        g_segB[o] = h[n];
    }
}

__global__ __launch_bounds__(256) void scan_pass2() {
    const int gidx = blockIdx.x * 256 + threadIdx.x;
    if (gidx >= BB * DIN) return;
    const int b = gidx / DIN;
    const int d = gidx % DIN;
    float h[NS];
#pragma unroll
    for (int n = 0; n < NS; n++) h[n] = 0.f;
    for (int s = 0; s < SEG; s++) {
#pragma unroll
        for (int n = 0; n < NS; n++) {
            const size_t o = ((size_t)((b * SEG + s) * NS + n)) * DIN + d;
            g_hin[o] = h[n];
            h[n] = g_segA[o] * h[n] + g_segB[o];
        }
    }
}

__global__ __launch_bounds__(128) void scan_pass3(const float* __restrict__ A_log,
                                                  const float* __restrict__ D_skip) {
    const int b = blockIdx.z;
    const int s = blockIdx.y;
    const int d = blockIdx.x * 128 + threadIdx.x;
    const int tid = threadIdx.x;
    const int l0 = s * SEGL;

    float A[NS];
#pragma unroll
    for (int n = 0; n < NS; n++) A[n] = -__expf(A_log[d * NS + n]);
    const float dsk = D_skip[d];

    float h[NS];
#pragma unroll
    for (int n = 0; n < NS; n++)
        h[n] = g_hin[((size_t)((b * SEG + s) * NS + n)) * DIN + d];

    __shared__ float sB[SEGL][NS];
    __shared__ float sC[SEGL][NS];
    for (int i = tid; i < SEGL * NS * 2; i += 128) {
        const int ll = i >> 4;
        const int c = i & 15;
        const float v = g_dbl[((size_t)(b * LL + l0 + ll)) * DBLW + RR + c];
        if (c < NS) sB[ll][c] = v;
        else        sC[ll][c - NS] = v;
    }
    __syncthreads();

    for (int j = 0; j < SEGL; j++) {
        const size_t rowb = ((size_t)(b * LL + l0 + j)) * DIN;
        const float dtv = g_dt[rowb + d];
        const float xv = __half2float(g_xconv[rowb + d]);
        const float dtx = dtv * xv;
        float yv = 0.f;
#pragma unroll
        for (int n = 0; n < NS; n++) {
            const float da = __expf(dtv * A[n]);
            h[n] = da * h[n] + dtx * sB[j][n];
            yv += h[n] * sC[j][n];
        }
        const float z = g_xz[((size_t)(b * LL + l0 + j)) * (2 * DIN) + DIN + d];
        const float sz = z / (1.f + __expf(-z));
        g_y[rowb + d] = __float2half_rn((yv + dsk * xv) * sz);
    }
}

// ---------------- launch ----------------
extern "C" void kernel_launch(void* const* d_in, const int* in_sizes, int n_in,
                              void* d_out, int out_size) {
    const float* hidden = (const float*)d_in[0];
    const float* norm_w = (const float*)d_in[1];
    const float* in_proj_w = (const float*)d_in[2];
    const float* conv_w = (const float*)d_in[3];
    const float* conv_b = (const float*)d_in[4];
    const float* x_proj_w = (const float*)d_in[5];
    const float* dt_proj_w = (const float*)d_in[6];
    const float* dt_proj_b = (const float*)d_in[7];
    const float* A_log = (const float*)d_in[8];
    const float* D_skip = (const float*)d_in[9];
    const float* out_proj_w = (const float*)d_in[10];
    float* out = (float*)d_out;

    __half *p_xnorm, *p_xconv, *p_dblh, *p_y;
    __half *p_w_in, *p_w_x, *p_w_dt, *p_w_out;
    float *p_dblp;
    cudaGetSymbolAddress((void**)&p_xnorm, g_xnorm);
    cudaGetSymbolAddress((void**)&p_xconv, g_xconv);
    cudaGetSymbolAddress((void**)&p_dblh, g_dblh);
    cudaGetSymbolAddress((void**)&p_y, g_y);
    cudaGetSymbolAddress((void**)&p_dblp, g_dblp);
    cudaGetSymbolAddress((void**)&p_w_in, g_w_in);
    cudaGetSymbolAddress((void**)&p_w_x, g_w_x);
    cudaGetSymbolAddress((void**)&p_w_dt, g_w_dt);
    cudaGetSymbolAddress((void**)&p_w_out, g_w_out);
    float *p_xz, *p_dt;
    cudaGetSymbolAddress((void**)&p_xz, g_xz);
    cudaGetSymbolAddress((void**)&p_dt, g_dt);

    cudaFuncSetAttribute(gemm_f16, cudaFuncAttributeMaxDynamicSharedMemorySize, GSMEM);

    const int M = MTOT;

    // 0a. big weights -> fp16 (launch 1)
    {
        const int total = (NWI + NWO) / 8;
        cvt_weights_big<<<(total + 255) / 256, 256>>>((const float4*)in_proj_w,
                                                      (const float4*)out_proj_w);
    }
    // 0b. small weights (launch 2)
    {
        const int total = (NWX + NWDT) / 8;
        cvt_weights_small<<<(total + 255) / 256, 256>>>((const float4*)x_proj_w,
                                                        (const float4*)dt_proj_w);
    }

    // 1. RMSNorm (launch 3)
    rmsnorm_kernel<<<M, 128>>>(hidden, norm_w);

    // 2. in_proj (launch 4 — ncu capture window)
    {
        dim3 grid(2 * DIN / 128, M / 128, 1);
        gemm_f16<<<grid, 256, GSMEM>>>(p_xnorm, DD, p_w_in, DD,
                                       p_xz, 2 * DIN, 0, DD, 2 * DIN, nullptr, 0);
    }

    // 3. conv + silu
    {
        const int total = (MTOT / 4) * (DIN / 8);
        conv_silu_kernel<<<(total + 255) / 256, 256>>>(conv_w, conv_b);
    }

    // 4. x_proj split-K (K=256 per split)
    {
        dim3 grid(1, M / 128, SPLITK);
        gemm_f16<<<grid, 256, GSMEM>>>(p_xconv, DIN, p_w_x, DIN,
                                       p_dblp, DBLW, (size_t)MTOT * DBLW,
                                       DIN / SPLITK, DBLW, nullptr, 0);
        reduce_dbl<<<(MTOT * DBLW + 255) / 256, 256>>>();
    }

    // 5. dt_proj + bias + softplus (K=64)
    {
        dim3 grid(DIN / 128, M / 128, 1);
        gemm_f16<<<grid, 256, GSMEM>>>(p_dblh, DBLW, p_w_dt, RR,
                                       p_dt, DIN, 0, RR, DIN, dt_proj_b, 1);
    }

    // 6. selective scan
    {
        dim3 grid1(DIN / 128, SEG, BB);
        scan_pass1<<<grid1, 128>>>(A_log);
        scan_pass2<<<(BB * DIN + 255) / 256, 256>>>();
        scan_pass3<<<grid1, 128>>>(A_log, D_skip);
    }

    // 7. out_proj
    {
        dim3 grid(DD / 128, M / 128, 1);
        gemm_f16<<<grid, 256, GSMEM>>>(p_y, DIN, p_w_out, DIN,
                                       out, DD, 0, DIN, DD, nullptr, 0);
    }
}

// round 13
// speedup vs baseline: 1.7817x; 1.0128x over previous
#include <cuda_runtime.h>
#include <cuda_fp16.h>
#include <math.h>
#include <stdint.h>

#define BB 4
#define LL 2048
#define DD 1024
#define DIN 1024
#define NS 8
#define RR 64
#define DBLW 80
#define SEG 32
#define SEGL (LL/SEG)     // 64
#define MTOT (BB*LL)
#define SPLITK 4

// ---------------- scratch ----------------
__device__ __half g_xnorm[MTOT*DD];
__device__ __half g_xz[MTOT*2*DIN];      // fp16 now
__device__ __half g_xconv[MTOT*DIN];
__device__ float  g_dbl[MTOT*DBLW];
__device__ __half g_dblh[MTOT*DBLW];
__device__ float  g_dblp[SPLITK*MTOT*DBLW];
__device__ float  g_dt[MTOT*DIN];
__device__ __half g_y[MTOT*DIN];
__device__ float  g_segA[BB*SEG*NS*DIN];
__device__ float  g_segB[BB*SEG*NS*DIN];
__device__ float  g_hin[BB*SEG*NS*DIN];
__device__ __half g_w_in[2*DIN*DD];
__device__ __half g_w_x[DBLW*DIN];
__device__ __half g_w_dt[DIN*RR];
__device__ __half g_w_out[DD*DIN];

// ---------------- helpers ----------------
__device__ __forceinline__ uint32_t pack_h2(float a, float b) {
    __half2 h = __floats2half2_rn(a, b);
    return *reinterpret_cast<uint32_t*>(&h);
}

__device__ __forceinline__ void mma_f16(float c[4], const uint32_t a[4], const uint32_t b[2]) {
    asm volatile(
        "mma.sync.aligned.m16n8k16.row.col.f32.f16.f16.f32 "
        "{%0,%1,%2,%3}, {%4,%5,%6,%7}, {%8,%9}, {%0,%1,%2,%3};"
        : "+f"(c[0]), "+f"(c[1]), "+f"(c[2]), "+f"(c[3])
        : "r"(a[0]), "r"(a[1]), "r"(a[2]), "r"(a[3]), "r"(b[0]), "r"(b[1]));
}

__device__ __forceinline__ void ldsm4(uint32_t r[4], uint32_t addr) {
    asm volatile("ldmatrix.sync.aligned.m8n8.x4.shared.b16 {%0,%1,%2,%3}, [%4];"
                 : "=r"(r[0]), "=r"(r[1]), "=r"(r[2]), "=r"(r[3]) : "r"(addr));
}

__device__ __forceinline__ void cp16(uint32_t dst, const void* src, bool v) {
    int sz = v ? 16 : 0;
    asm volatile("cp.async.cg.shared.global [%0], [%1], 16, %2;\n"
                 :: "r"(dst), "l"(src), "r"(sz));
}

// ---------------- weight convert (fp32 -> fp16) ----------------
#define NWI (2*DIN*DD)
#define NWX (DBLW*DIN)
#define NWDT (DIN*RR)
#define NWO (DD*DIN)

__global__ __launch_bounds__(256) void cvt_weights_big(const float4* __restrict__ iw,
                                                       const float4* __restrict__ ow) {
    int i = blockIdx.x * 256 + threadIdx.x;
    const float4* src;
    uint4* dst;
    if (i < NWI/8) { src = iw + 2*i; dst = (uint4*)g_w_in + i; }
    else if ((i -= NWI/8) < NWO/8) { src = ow + 2*i; dst = (uint4*)g_w_out + i; }
    else return;
    const float4 a = src[0], b = src[1];
    uint4 v;
    v.x = pack_h2(a.x, a.y); v.y = pack_h2(a.z, a.w);
    v.z = pack_h2(b.x, b.y); v.w = pack_h2(b.z, b.w);
    *dst = v;
}

__global__ __launch_bounds__(256) void cvt_weights_small(const float4* __restrict__ xw,
                                                         const float4* __restrict__ dw) {
    int i = blockIdx.x * 256 + threadIdx.x;
    const float4* src;
    uint4* dst;
    if (i < NWX/8) { src = xw + 2*i; dst = (uint4*)g_w_x + i; }
    else if ((i -= NWX/8) < NWDT/8) { src = dw + 2*i; dst = (uint4*)g_w_dt + i; }
    else return;
    const float4 a = src[0], b = src[1];
    uint4 v;
    v.x = pack_h2(a.x, a.y); v.y = pack_h2(a.z, a.w);
    v.z = pack_h2(b.x, b.y); v.w = pack_h2(b.z, b.w);
    *dst = v;
}

// ---------------- RMSNorm (fp16 output) ----------------
__global__ __launch_bounds__(128) void rmsnorm_kernel(const float* __restrict__ x,
                                                      const float* __restrict__ w) {
    const int row = blockIdx.x;
    const int t = threadIdx.x;
    const float4* xr4 = (const float4*)(x + (size_t)row * DD);
    const float4 v0 = xr4[2*t], v1 = xr4[2*t + 1];
    float ss = v0.x*v0.x + v0.y*v0.y + v0.z*v0.z + v0.w*v0.w
             + v1.x*v1.x + v1.y*v1.y + v1.z*v1.z + v1.w*v1.w;
#pragma unroll
    for (int o = 16; o > 0; o >>= 1) ss += __shfl_xor_sync(0xffffffffu, ss, o);
    __shared__ float red[4];
    if ((t & 31) == 0) red[t >> 5] = ss;
    __syncthreads();
    const float tot = red[0] + red[1] + red[2] + red[3];
    const float sc = rsqrtf(tot * (1.f / DD) + 1e-5f);
    const float4 w0 = ((const float4*)w)[2*t], w1 = ((const float4*)w)[2*t + 1];
    uint4 v;
    v.x = pack_h2(v0.x * sc * w0.x, v0.y * sc * w0.y);
    v.y = pack_h2(v0.z * sc * w0.z, v0.w * sc * w0.w);
    v.z = pack_h2(v1.x * sc * w1.x, v1.y * sc * w1.y);
    v.w = pack_h2(v1.z * sc * w1.z, v1.w * sc * w1.w);
    ((uint4*)(g_xnorm + (size_t)row * DD))[t] = v;
}

// ---------------- FP16 GEMM + ldmatrix: BM=BN=128, BK=64h, 256 thr, 8 warps 32x64 ----------------
// TO: output type (float or __half). EPI: 0 plain, 1 softplus(+bias).
#define GSTAGES 3
#define SWORDS (128*36)
#define STGB (SWORDS*4)          // 18432 B
#define GSMEM (2*GSTAGES*STGB)   // 110592 B

template<typename TO, int EPI>
__global__ __launch_bounds__(256, 2) void gemm_f16(
    const __half* __restrict__ A, int lda,
    const __half* __restrict__ W, int ldw,
    TO* __restrict__ C, int ldc, size_t cstride,
    int K, int E,
    const float* __restrict__ bias)
{
    extern __shared__ uint32_t smw[];
    uint32_t* sA = smw;
    uint32_t* sB = smw + GSTAGES * SWORDS;

    const int tid = threadIdx.x;
    const int lane = tid & 31;
    const int wid = tid >> 5;
    const int m0 = blockIdx.y * 128;
    const int e0 = blockIdx.x * 128;
    const int z = blockIdx.z;
    const int mw = (wid & 3) * 32;
    const int nw = (wid >> 2) * 64;

    const int prow = tid >> 3;
    const int pk = (tid & 7) * 8;

    const __half* aP[4];
    const __half* wP[4];
    bool wv[4];
    uint32_t dAo[4], dBo[4];
    const uint32_t sAu = (uint32_t)__cvta_generic_to_shared(sA);
    const uint32_t sBu = (uint32_t)__cvta_generic_to_shared(sB);
#pragma unroll
    for (int c = 0; c < 4; c++) {
        const int r = prow + 32 * c;
        aP[c] = A + (size_t)(m0 + r) * lda + (size_t)z * K + pk;
        const int er = e0 + r;
        wv[c] = er < E;
        wP[c] = W + (size_t)(wv[c] ? er : 0) * ldw + (size_t)z * K + pk;
        dAo[c] = sAu + (r * 36 + (tid & 7) * 4) * 4;
        dBo[c] = sBu + (r * 36 + (tid & 7) * 4) * 4;
    }

    const int quad = lane >> 3;
    const int qrow = lane & 7;
    uint32_t aoff[2];
#pragma unroll
    for (int mt = 0; mt < 2; mt++) {
        const int row = mw + mt * 16 + (quad & 1) * 8 + qrow;
        aoff[mt] = (uint32_t)(row * 36 + (quad >> 1) * 4);
    }
    uint32_t boff[4];
#pragma unroll
    for (int np = 0; np < 4; np++) {
        const int row = nw + np * 16 + (quad >> 1) * 8 + qrow;
        boff[np] = (uint32_t)(row * 36 + (quad & 1) * 4);
    }

    float acc[2][8][4];
#pragma unroll
    for (int i = 0; i < 2; i++)
#pragma unroll
        for (int j = 0; j < 8; j++)
#pragma unroll
            for (int l = 0; l < 4; l++) acc[i][j][l] = 0.f;

    const int T = K / 64;

#pragma unroll
    for (int p = 0; p < GSTAGES - 1; p++) {
        if (p < T) {
            const int ko = p * 64;
#pragma unroll
            for (int c = 0; c < 4; c++) {
                cp16(dAo[c] + p * STGB, aP[c] + ko, true);
                cp16(dBo[c] + p * STGB, wP[c] + ko, wv[c]);
            }
        }
        asm volatile("cp.async.commit_group;\n");
    }

    for (int t = 0; t < T; t++) {
        asm volatile("cp.async.wait_group 1;\n");
        __syncthreads();

        {
            const int tn = t + GSTAGES - 1;
            if (tn < T) {
                const int ko = tn * 64;
                const int so = tn % GSTAGES;
#pragma unroll
                for (int c = 0; c < 4; c++) {
                    cp16(dAo[c] + so * STGB, aP[c] + ko, true);
                    cp16(dBo[c] + so * STGB, wP[c] + ko, wv[c]);
                }
            }
            asm volatile("cp.async.commit_group;\n");
        }

        const int stg = t % GSTAGES;
        const uint32_t stgw = (uint32_t)(stg * SWORDS);
        const uint32_t aBase = sAu + stgw * 4;
        const uint32_t bBase = sBu + stgw * 4;

#pragma unroll
        for (int ks = 0; ks < 4; ks++) {
            const uint32_t kk4 = (uint32_t)(ks * 8) * 4;
            uint32_t af[2][4];
            uint32_t bq[4][4];
#pragma unroll
            for (int mt = 0; mt < 2; mt++)
                ldsm4(af[mt], aBase + (aoff[mt] * 4) + kk4);
#pragma unroll
            for (int np = 0; np < 4; np++)
                ldsm4(bq[np], bBase + (boff[np] * 4) + kk4);

#pragma unroll
            for (int mt = 0; mt < 2; mt++)
#pragma unroll
                for (int np = 0; np < 4; np++) {
                    mma_f16(acc[mt][2*np],     af[mt], &bq[np][0]);
                    mma_f16(acc[mt][2*np + 1], af[mt], &bq[np][2]);
                }
        }
    }

    // epilogue
    const int g = lane >> 2;
    const int tg = lane & 3;
    TO* Cz = C + (size_t)z * cstride;
#pragma unroll
    for (int mt = 0; mt < 2; mt++) {
        const int r0 = m0 + mw + mt * 16 + g;
        const int r1 = r0 + 8;
#pragma unroll
        for (int nt = 0; nt < 8; nt++) {
            const int c0 = e0 + nw + nt * 8 + tg * 2;
            if (c0 < E) {
                float va0 = acc[mt][nt][0], va1 = acc[mt][nt][1];
                float vb0 = acc[mt][nt][2], vb1 = acc[mt][nt][3];
                if (EPI == 1) {
                    const float b0 = bias[c0], b1 = bias[c0 + 1];
                    va0 += b0; va0 = fmaxf(va0, 0.f) + log1pf(__expf(-fabsf(va0)));
                    va1 += b1; va1 = fmaxf(va1, 0.f) + log1pf(__expf(-fabsf(va1)));
                    vb0 += b0; vb0 = fmaxf(vb0, 0.f) + log1pf(__expf(-fabsf(vb0)));
                    vb1 += b1; vb1 = fmaxf(vb1, 0.f) + log1pf(__expf(-fabsf(vb1)));
                }
                if (sizeof(TO) == 2) {
                    *(uint32_t*)((__half*)Cz + (size_t)r0 * ldc + c0) = pack_h2(va0, va1);
                    *(uint32_t*)((__half*)Cz + (size_t)r1 * ldc + c0) = pack_h2(vb0, vb1);
                } else {
                    *(float2*)((float*)Cz + (size_t)r0 * ldc + c0) = make_float2(va0, va1);
                    *(float2*)((float*)Cz + (size_t)r1 * ldc + c0) = make_float2(vb0, vb1);
                }
            }
        }
    }
}

// ---------------- split-K reduce for x_proj ----------------
__global__ __launch_bounds__(256) void reduce_dbl() {
    const int idx = blockIdx.x * 256 + threadIdx.x;
    if (idx >= MTOT * DBLW) return;
    float s = 0.f;
#pragma unroll
    for (int p = 0; p < SPLITK; p++) s += g_dblp[(size_t)p * MTOT * DBLW + idx];
    g_dbl[idx] = s;
    g_dblh[idx] = __float2half_rn(s);
}

// ---------------- conv+silu: 4 rows x 8 ch, fp16 in/out ----------------
__global__ __launch_bounds__(256) void conv_silu_kernel(const float* __restrict__ conv_w,
                                                        const float* __restrict__ conv_b) {
    const int t = blockIdx.x * 256 + threadIdx.x;
    const int nd8 = DIN / 8;
    const int d0 = (t % nd8) * 8;
    const int m0 = (t / nd8) * 4;
    if (m0 >= MTOT) return;
    const int l0 = m0 % LL;
    const int b = m0 / LL;

    float xv[7][8];
#pragma unroll
    for (int j = 0; j < 7; j++) {
        const int ls = l0 - 3 + j;
        if (ls >= 0) {
            const uint4 raw = *(const uint4*)(g_xz + ((size_t)(b * LL + ls)) * (2 * DIN) + d0);
            const __half2* hp = (const __half2*)&raw;
#pragma unroll
            for (int q = 0; q < 4; q++) {
                const float2 f = __half22float2(hp[q]);
                xv[j][2*q] = f.x;
                xv[j][2*q + 1] = f.y;
            }
        } else {
#pragma unroll
            for (int c = 0; c < 8; c++) xv[j][c] = 0.f;
        }
    }
    float4 wr[8];
#pragma unroll
    for (int c = 0; c < 8; c++) wr[c] = *(const float4*)(conv_w + (d0 + c) * 4);
    float bi[8];
#pragma unroll
    for (int c = 0; c < 8; c++) bi[c] = conv_b[d0 + c];

#pragma unroll
    for (int i = 0; i < 4; i++) {
        float o[8];
#pragma unroll
        for (int c = 0; c < 8; c++) {
            o[c] = bi[c] + ((const float*)&wr[c])[0] * xv[i][c]
                         + ((const float*)&wr[c])[1] * xv[i+1][c]
                         + ((const float*)&wr[c])[2] * xv[i+2][c]
                         + ((const float*)&wr[c])[3] * xv[i+3][c];
            o[c] = o[c] / (1.f + __expf(-o[c]));
        }
        uint4 v;
        v.x = pack_h2(o[0], o[1]); v.y = pack_h2(o[2], o[3]);
        v.z = pack_h2(o[4], o[5]); v.w = pack_h2(o[6], o[7]);
        *(uint4*)(g_xconv + ((size_t)(m0 + i)) * DIN + d0) = v;
    }
}

// ---------------- chunked selective scan (SEG=32) ----------------
__global__ __launch_bounds__(128) void scan_pass1(const float* __restrict__ A_log) {
    const int b = blockIdx.z;
    const int s = blockIdx.y;
    const int d = blockIdx.x * 128 + threadIdx.x;
    const int tid = threadIdx.x;
    const int l0 = s * SEGL;

    float A[NS];
#pragma unroll
    for (int n = 0; n < NS; n++) A[n] = -__expf(A_log[d * NS + n]);

    float p[NS], h[NS];
#pragma unroll
    for (int n = 0; n < NS; n++) { p[n] = 1.f; h[n] = 0.f; }

    __shared__ float sB[SEGL][NS];
    for (int i = tid; i < SEGL * NS; i += 128) {
        const int ll = i >> 3;
        const int n = i & 7;
        sB[ll][n] = g_dbl[((size_t)(b * LL + l0 + ll)) * DBLW + RR + n];
    }
    __syncthreads();

    for (int j = 0; j < SEGL; j++) {
        const size_t rowb = ((size_t)(b * LL + l0 + j)) * DIN;
        const float dtv = g_dt[rowb + d];
        const float xv = __half2float(g_xconv[rowb + d]);
        const float dtx = dtv * xv;
#pragma unroll
        for (int n = 0; n < NS; n++) {
            const float da = __expf(dtv * A[n]);
            p[n] *= da;
            h[n] = da * h[n] + dtx * sB[j][n];
        }
    }
#pragma unroll
    for (int n = 0; n < NS; n++) {
        const size_t o = ((size_t)((b * SEG + s) * NS + n)) * DIN + d;
        g_segA[o] = p[n];
        g_segB[o] = h[n];
    }
}

__global__ __launch_bounds__(256) void scan_pass2() {
    const int gidx = blockIdx.x * 256 + threadIdx.x;
    if (gidx >= BB * DIN) return;
    const int b = gidx / DIN;
    const int d = gidx % DIN;
    float h[NS];
#pragma unroll
    for (int n = 0; n < NS; n++) h[n] = 0.f;
    for (int s = 0; s < SEG; s++) {
#pragma unroll
        for (int n = 0; n < NS; n++) {
            const size_t o = ((size_t)((b * SEG + s) * NS + n)) * DIN + d;
            g_hin[o] = h[n];
            h[n] = g_segA[o] * h[n] + g_segB[o];
        }
    }
}

__global__ __launch_bounds__(128) void scan_pass3(const float* __restrict__ A_log,
                                                  const float* __restrict__ D_skip) {
    const int b = blockIdx.z;
    const int s = blockIdx.y;
    const int d = blockIdx.x * 128 + threadIdx.x;
    const int tid = threadIdx.x;
    const int l0 = s * SEGL;

    float A[NS];
#pragma unroll
    for (int n = 0; n < NS; n++) A[n] = -__expf(A_log[d * NS + n]);
    const float dsk = D_skip[d];

    float h[NS];
#pragma unroll
    for (int n = 0; n < NS; n++)
        h[n] = g_hin[((size_t)((b * SEG + s) * NS + n)) * DIN + d];

    __shared__ float sB[SEGL][NS];
    __shared__ float sC[SEGL][NS];
    for (int i = tid; i < SEGL * NS * 2; i += 128) {
        const int ll = i >> 4;
        const int c = i & 15;
        const float v = g_dbl[((size_t)(b * LL + l0 + ll)) * DBLW + RR + c];
        if (c < NS) sB[ll][c] = v;
        else        sC[ll][c - NS] = v;
    }
    __syncthreads();

    for (int j = 0; j < SEGL; j++) {
        const size_t rowb = ((size_t)(b * LL + l0 + j)) * DIN;
        const float dtv = g_dt[rowb + d];
        const float xv = __half2float(g_xconv[rowb + d]);
        const float dtx = dtv * xv;
        float yv = 0.f;
#pragma unroll
        for (int n = 0; n < NS; n++) {
            const float da = __expf(dtv * A[n]);
            h[n] = da * h[n] + dtx * sB[j][n];
            yv += h[n] * sC[j][n];
        }
        const float z = __half2float(g_xz[((size_t)(b * LL + l0 + j)) * (2 * DIN) + DIN + d]);
        const float sz = z / (1.f + __expf(-z));
        g_y[rowb + d] = __float2half_rn((yv + dsk * xv) * sz);
    }
}

// ---------------- launch ----------------
extern "C" void kernel_launch(void* const* d_in, const int* in_sizes, int n_in,
                              void* d_out, int out_size) {
    const float* hidden = (const float*)d_in[0];
    const float* norm_w = (const float*)d_in[1];
    const float* in_proj_w = (const float*)d_in[2];
    const float* conv_w = (const float*)d_in[3];
    const float* conv_b = (const float*)d_in[4];
    const float* x_proj_w = (const float*)d_in[5];
    const float* dt_proj_w = (const float*)d_in[6];
    const float* dt_proj_b = (const float*)d_in[7];
    const float* A_log = (const float*)d_in[8];
    const float* D_skip = (const float*)d_in[9];
    const float* out_proj_w = (const float*)d_in[10];
    float* out = (float*)d_out;

    __half *p_xnorm, *p_xz, *p_xconv, *p_dblh, *p_y;
    __half *p_w_in, *p_w_x, *p_w_dt, *p_w_out;
    float *p_dblp, *p_dt;
    cudaGetSymbolAddress((void**)&p_xnorm, g_xnorm);
    cudaGetSymbolAddress((void**)&p_xz, g_xz);
    cudaGetSymbolAddress((void**)&p_xconv, g_xconv);
    cudaGetSymbolAddress((void**)&p_dblh, g_dblh);
    cudaGetSymbolAddress((void**)&p_y, g_y);
    cudaGetSymbolAddress((void**)&p_dblp, g_dblp);
    cudaGetSymbolAddress((void**)&p_dt, g_dt);
    cudaGetSymbolAddress((void**)&p_w_in, g_w_in);
    cudaGetSymbolAddress((void**)&p_w_x, g_w_x);
    cudaGetSymbolAddress((void**)&p_w_dt, g_w_dt);
    cudaGetSymbolAddress((void**)&p_w_out, g_w_out);

    cudaFuncSetAttribute(gemm_f16<__half, 0>, cudaFuncAttributeMaxDynamicSharedMemorySize, GSMEM);
    cudaFuncSetAttribute(gemm_f16<float, 0>, cudaFuncAttributeMaxDynamicSharedMemorySize, GSMEM);
    cudaFuncSetAttribute(gemm_f16<float, 1>, cudaFuncAttributeMaxDynamicSharedMemorySize, GSMEM);

    const int M = MTOT;

    // 0a. big weights -> fp16 (launch 1)
    {
        const int total = (NWI + NWO) / 8;
        cvt_weights_big<<<(total + 255) / 256, 256>>>((const float4*)in_proj_w,
                                                      (const float4*)out_proj_w);
    }
    // 0b. small weights (launch 2)
    {
        const int total = (NWX + NWDT) / 8;
        cvt_weights_small<<<(total + 255) / 256, 256>>>((const float4*)x_proj_w,
                                                        (const float4*)dt_proj_w);
    }

    // 1. RMSNorm (launch 3)
    rmsnorm_kernel<<<M, 128>>>(hidden, norm_w);

    // 2. in_proj (launch 4 — ncu capture window) — fp16 output
    {
        dim3 grid(2 * DIN / 128, M / 128, 1);
        gemm_f16<__half, 0><<<grid, 256, GSMEM>>>(p_xnorm, DD, p_w_in, DD,
                                                  p_xz, 2 * DIN, 0, DD, 2 * DIN, nullptr);
    }

    // 3. conv + silu
    {
        const int total = (MTOT / 4) * (DIN / 8);
        conv_silu_kernel<<<(total + 255) / 256, 256>>>(conv_w, conv_b);
    }

    // 4. x_proj split-K (K=256 per split)
    {
        dim3 grid(1, M / 128, SPLITK);
        gemm_f16<float, 0><<<grid, 256, GSMEM>>>(p_xconv, DIN, p_w_x, DIN,
                                                 p_dblp, DBLW, (size_t)MTOT * DBLW,
                                                 DIN / SPLITK, DBLW, nullptr);
        reduce_dbl<<<(MTOT * DBLW + 255) / 256, 256>>>();
    }

    // 5. dt_proj + bias + softplus (K=64)
    {
        dim3 grid(DIN / 128, M / 128, 1);
        gemm_f16<float, 1><<<grid, 256, GSMEM>>>(p_dblh, DBLW, p_w_dt, RR,
                                                 p_dt, DIN, 0, RR, DIN, dt_proj_b);
    }

    // 6. selective scan
    {
        dim3 grid1(DIN / 128, SEG, BB);
        scan_pass1<<<grid1, 128>>>(A_log);
        scan_pass2<<<(BB * DIN + 255) / 256, 256>>>();
        scan_pass3<<<grid1, 128>>>(A_log, D_skip);
    }

    // 7. out_proj (fp32 output)
    {
        dim3 grid(DD / 128, M / 128, 1);
        gemm_f16<float, 0><<<grid, 256, GSMEM>>>(p_y, DIN, p_w_out, DIN,
                                                 out, DD, 0, DIN, DD, nullptr);
    }
}

// round 14
// speedup vs baseline: 1.9744x; 1.1082x over previous
#include <cuda_runtime.h>
#include <cuda_fp16.h>
#include <math.h>
#include <stdint.h>

#define BB 4
#define LL 2048
#define DD 1024
#define DIN 1024
#define NS 8
#define RR 64
#define DBLW 80
#define SEG 32
#define SEGL (LL/SEG)     // 64
#define MTOT (BB*LL)
#define SPLITK 4

// ---------------- scratch ----------------
__device__ __half g_xnorm[MTOT*DD];
__device__ __half g_xz[MTOT*2*DIN];
__device__ __half g_xconv[MTOT*DIN];
__device__ float  g_dbl[MTOT*DBLW];
__device__ __half g_dblh[MTOT*DBLW];
__device__ float  g_dblp[SPLITK*MTOT*DBLW];
__device__ __half g_dt[MTOT*DIN];        // fp16 now
__device__ __half g_y[MTOT*DIN];
__device__ float  g_segA[BB*SEG*NS*DIN];
__device__ float  g_segB[BB*SEG*NS*DIN];
__device__ float  g_hin[BB*SEG*NS*DIN];
__device__ __half g_w_in[2*DIN*DD];
__device__ __half g_w_x[DBLW*DIN];
__device__ __half g_w_dt[DIN*RR];
__device__ __half g_w_out[DD*DIN];

// ---------------- helpers ----------------
__device__ __forceinline__ uint32_t pack_h2(float a, float b) {
    __half2 h = __floats2half2_rn(a, b);
    return *reinterpret_cast<uint32_t*>(&h);
}

__device__ __forceinline__ void mma_f16(float c[4], const uint32_t a[4], const uint32_t b[2]) {
    asm volatile(
        "mma.sync.aligned.m16n8k16.row.col.f32.f16.f16.f32 "
        "{%0,%1,%2,%3}, {%4,%5,%6,%7}, {%8,%9}, {%0,%1,%2,%3};"
        : "+f"(c[0]), "+f"(c[1]), "+f"(c[2]), "+f"(c[3])
        : "r"(a[0]), "r"(a[1]), "r"(a[2]), "r"(a[3]), "r"(b[0]), "r"(b[1]));
}

__device__ __forceinline__ void ldsm4(uint32_t r[4], uint32_t addr) {
    asm volatile("ldmatrix.sync.aligned.m8n8.x4.shared.b16 {%0,%1,%2,%3}, [%4];"
                 : "=r"(r[0]), "=r"(r[1]), "=r"(r[2]), "=r"(r[3]) : "r"(addr));
}

__device__ __forceinline__ void cp16(uint32_t dst, const void* src, bool v) {
    int sz = v ? 16 : 0;
    asm volatile("cp.async.cg.shared.global [%0], [%1], 16, %2;\n"
                 :: "r"(dst), "l"(src), "r"(sz));
}

// da[n] = exp(dtv * A[n]); fast path when A[n] == -(n+1) (structured S4D init)
__device__ __forceinline__ void calc_da(float da[NS], float dtv,
                                        const float A[NS], bool structured) {
    if (structured) {
        const float e1 = __expf(-dtv);
        const float e2 = e1 * e1;
        const float e4 = e2 * e2;
        da[0] = e1;       da[1] = e2;
        da[2] = e2 * e1;  da[3] = e4;
        da[4] = e4 * e1;  da[5] = e4 * e2;
        da[6] = e4 * e2 * e1;
        da[7] = e4 * e4;
    } else {
#pragma unroll
        for (int n = 0; n < NS; n++) da[n] = __expf(dtv * A[n]);
    }
}

// ---------------- weight convert (fp32 -> fp16) ----------------
#define NWI (2*DIN*DD)
#define NWX (DBLW*DIN)
#define NWDT (DIN*RR)
#define NWO (DD*DIN)

__global__ __launch_bounds__(256) void cvt_weights_big(const float4* __restrict__ iw,
                                                       const float4* __restrict__ ow) {
    int i = blockIdx.x * 256 + threadIdx.x;
    const float4* src;
    uint4* dst;
    if (i < NWI/8) { src = iw + 2*i; dst = (uint4*)g_w_in + i; }
    else if ((i -= NWI/8) < NWO/8) { src = ow + 2*i; dst = (uint4*)g_w_out + i; }
    else return;
    const float4 a = src[0], b = src[1];
    uint4 v;
    v.x = pack_h2(a.x, a.y); v.y = pack_h2(a.z, a.w);
    v.z = pack_h2(b.x, b.y); v.w = pack_h2(b.z, b.w);
    *dst = v;
}

__global__ __launch_bounds__(256) void cvt_weights_small(const float4* __restrict__ xw,
                                                         const float4* __restrict__ dw) {
    int i = blockIdx.x * 256 + threadIdx.x;
    const float4* src;
    uint4* dst;
    if (i < NWX/8) { src = xw + 2*i; dst = (uint4*)g_w_x + i; }
    else if ((i -= NWX/8) < NWDT/8) { src = dw + 2*i; dst = (uint4*)g_w_dt + i; }
    else return;
    const float4 a = src[0], b = src[1];
    uint4 v;
    v.x = pack_h2(a.x, a.y); v.y = pack_h2(a.z, a.w);
    v.z = pack_h2(b.x, b.y); v.w = pack_h2(b.z, b.w);
    *dst = v;
}

// ---------------- RMSNorm (fp16 output) ----------------
__global__ __launch_bounds__(128) void rmsnorm_kernel(const float* __restrict__ x,
                                                      const float* __restrict__ w) {
    const int row = blockIdx.x;
    const int t = threadIdx.x;
    const float4* xr4 = (const float4*)(x + (size_t)row * DD);
    const float4 v0 = xr4[2*t], v1 = xr4[2*t + 1];
    float ss = v0.x*v0.x + v0.y*v0.y + v0.z*v0.z + v0.w*v0.w
             + v1.x*v1.x + v1.y*v1.y + v1.z*v1.z + v1.w*v1.w;
#pragma unroll
    for (int o = 16; o > 0; o >>= 1) ss += __shfl_xor_sync(0xffffffffu, ss, o);
    __shared__ float red[4];
    if ((t & 31) == 0) red[t >> 5] = ss;
    __syncthreads();
    const float tot = red[0] + red[1] + red[2] + red[3];
    const float sc = rsqrtf(tot * (1.f / DD) + 1e-5f);
    const float4 w0 = ((const float4*)w)[2*t], w1 = ((const float4*)w)[2*t + 1];
    uint4 v;
    v.x = pack_h2(v0.x * sc * w0.x, v0.y * sc * w0.y);
    v.y = pack_h2(v0.z * sc * w0.z, v0.w * sc * w0.w);
    v.z = pack_h2(v1.x * sc * w1.x, v1.y * sc * w1.y);
    v.w = pack_h2(v1.z * sc * w1.z, v1.w * sc * w1.w);
    ((uint4*)(g_xnorm + (size_t)row * DD))[t] = v;
}

// ---------------- FP16 GEMM + ldmatrix: BM=BN=128, BK=64h, 256 thr, 8 warps 32x64 ----------------
#define GSTAGES 3
#define SWORDS (128*36)
#define STGB (SWORDS*4)
#define GSMEM (2*GSTAGES*STGB)   // 110592 B

template<typename TO, int EPI>
__global__ __launch_bounds__(256, 2) void gemm_f16(
    const __half* __restrict__ A, int lda,
    const __half* __restrict__ W, int ldw,
    TO* __restrict__ C, int ldc, size_t cstride,
    int K, int E,
    const float* __restrict__ bias)
{
    extern __shared__ uint32_t smw[];
    uint32_t* sA = smw;
    uint32_t* sB = smw + GSTAGES * SWORDS;

    const int tid = threadIdx.x;
    const int lane = tid & 31;
    const int wid = tid >> 5;
    const int m0 = blockIdx.y * 128;
    const int e0 = blockIdx.x * 128;
    const int z = blockIdx.z;
    const int mw = (wid & 3) * 32;
    const int nw = (wid >> 2) * 64;

    const int prow = tid >> 3;
    const int pk = (tid & 7) * 8;

    const __half* aP[4];
    const __half* wP[4];
    bool wv[4];
    uint32_t dAo[4], dBo[4];
    const uint32_t sAu = (uint32_t)__cvta_generic_to_shared(sA);
    const uint32_t sBu = (uint32_t)__cvta_generic_to_shared(sB);
#pragma unroll
    for (int c = 0; c < 4; c++) {
        const int r = prow + 32 * c;
        aP[c] = A + (size_t)(m0 + r) * lda + (size_t)z * K + pk;
        const int er = e0 + r;
        wv[c] = er < E;
        wP[c] = W + (size_t)(wv[c] ? er : 0) * ldw + (size_t)z * K + pk;
        dAo[c] = sAu + (r * 36 + (tid & 7) * 4) * 4;
        dBo[c] = sBu + (r * 36 + (tid & 7) * 4) * 4;
    }

    const int quad = lane >> 3;
    const int qrow = lane & 7;
    uint32_t aoff[2];
#pragma unroll
    for (int mt = 0; mt < 2; mt++) {
        const int row = mw + mt * 16 + (quad & 1) * 8 + qrow;
        aoff[mt] = (uint32_t)(row * 36 + (quad >> 1) * 4);
    }
    uint32_t boff[4];
#pragma unroll
    for (int np = 0; np < 4; np++) {
        const int row = nw + np * 16 + (quad >> 1) * 8 + qrow;
        boff[np] = (uint32_t)(row * 36 + (quad & 1) * 4);
    }

    float acc[2][8][4];
#pragma unroll
    for (int i = 0; i < 2; i++)
#pragma unroll
        for (int j = 0; j < 8; j++)
#pragma unroll
            for (int l = 0; l < 4; l++) acc[i][j][l] = 0.f;

    const int T = K / 64;

#pragma unroll
    for (int p = 0; p < GSTAGES - 1; p++) {
        if (p < T) {
            const int ko = p * 64;
#pragma unroll
            for (int c = 0; c < 4; c++) {
                cp16(dAo[c] + p * STGB, aP[c] + ko, true);
                cp16(dBo[c] + p * STGB, wP[c] + ko, wv[c]);
            }
        }
        asm volatile("cp.async.commit_group;\n");
    }

    for (int t = 0; t < T; t++) {
        asm volatile("cp.async.wait_group 1;\n");
        __syncthreads();

        {
            const int tn = t + GSTAGES - 1;
            if (tn < T) {
                const int ko = tn * 64;
                const int so = tn % GSTAGES;
#pragma unroll
                for (int c = 0; c < 4; c++) {
                    cp16(dAo[c] + so * STGB, aP[c] + ko, true);
                    cp16(dBo[c] + so * STGB, wP[c] + ko, wv[c]);
                }
            }
            asm volatile("cp.async.commit_group;\n");
        }

        const int stg = t % GSTAGES;
        const uint32_t stgw = (uint32_t)(stg * SWORDS);
        const uint32_t aBase = sAu + stgw * 4;
        const uint32_t bBase = sBu + stgw * 4;

#pragma unroll
        for (int ks = 0; ks < 4; ks++) {
            const uint32_t kk4 = (uint32_t)(ks * 8) * 4;
            uint32_t af[2][4];
            uint32_t bq[4][4];
#pragma unroll
            for (int mt = 0; mt < 2; mt++)
                ldsm4(af[mt], aBase + (aoff[mt] * 4) + kk4);
#pragma unroll
            for (int np = 0; np < 4; np++)
                ldsm4(bq[np], bBase + (boff[np] * 4) + kk4);

#pragma unroll
            for (int mt = 0; mt < 2; mt++)
#pragma unroll
                for (int np = 0; np < 4; np++) {
                    mma_f16(acc[mt][2*np],     af[mt], &bq[np][0]);
                    mma_f16(acc[mt][2*np + 1], af[mt], &bq[np][2]);
                }
        }
    }

    // epilogue
    const int g = lane >> 2;
    const int tg = lane & 3;
    TO* Cz = C + (size_t)z * cstride;
#pragma unroll
    for (int mt = 0; mt < 2; mt++) {
        const int r0 = m0 + mw + mt * 16 + g;
        const int r1 = r0 + 8;
#pragma unroll
        for (int nt = 0; nt < 8; nt++) {
            const int c0 = e0 + nw + nt * 8 + tg * 2;
            if (c0 < E) {
                float va0 = acc[mt][nt][0], va1 = acc[mt][nt][1];
                float vb0 = acc[mt][nt][2], vb1 = acc[mt][nt][3];
                if (EPI == 1) {
                    const float b0 = bias[c0], b1 = bias[c0 + 1];
                    va0 += b0; va0 = fmaxf(va0, 0.f) + log1pf(__expf(-fabsf(va0)));
                    va1 += b1; va1 = fmaxf(va1, 0.f) + log1pf(__expf(-fabsf(va1)));
                    vb0 += b0; vb0 = fmaxf(vb0, 0.f) + log1pf(__expf(-fabsf(vb0)));
                    vb1 += b1; vb1 = fmaxf(vb1, 0.f) + log1pf(__expf(-fabsf(vb1)));
                }
                if (sizeof(TO) == 2) {
                    *(uint32_t*)((__half*)Cz + (size_t)r0 * ldc + c0) = pack_h2(va0, va1);
                    *(uint32_t*)((__half*)Cz + (size_t)r1 * ldc + c0) = pack_h2(vb0, vb1);
                } else {
                    *(float2*)((float*)Cz + (size_t)r0 * ldc + c0) = make_float2(va0, va1);
                    *(float2*)((float*)Cz + (size_t)r1 * ldc + c0) = make_float2(vb0, vb1);
                }
            }
        }
    }
}

// ---------------- split-K reduce for x_proj ----------------
__global__ __launch_bounds__(256) void reduce_dbl() {
    const int idx = blockIdx.x * 256 + threadIdx.x;
    if (idx >= MTOT * DBLW) return;
    float s = 0.f;
#pragma unroll
    for (int p = 0; p < SPLITK; p++) s += g_dblp[(size_t)p * MTOT * DBLW + idx];
    g_dbl[idx] = s;
    g_dblh[idx] = __float2half_rn(s);
}

// ---------------- conv+silu: 4 rows x 8 ch, fp16 in/out ----------------
__global__ __launch_bounds__(256) void conv_silu_kernel(const float* __restrict__ conv_w,
                                                        const float* __restrict__ conv_b) {
    const int t = blockIdx.x * 256 + threadIdx.x;
    const int nd8 = DIN / 8;
    const int d0 = (t % nd8) * 8;
    const int m0 = (t / nd8) * 4;
    if (m0 >= MTOT) return;
    const int l0 = m0 % LL;
    const int b = m0 / LL;

    float xv[7][8];
#pragma unroll
    for (int j = 0; j < 7; j++) {
        const int ls = l0 - 3 + j;
        if (ls >= 0) {
            const uint4 raw = *(const uint4*)(g_xz + ((size_t)(b * LL + ls)) * (2 * DIN) + d0);
            const __half2* hp = (const __half2*)&raw;
#pragma unroll
            for (int q = 0; q < 4; q++) {
                const float2 f = __half22float2(hp[q]);
                xv[j][2*q] = f.x;
                xv[j][2*q + 1] = f.y;
            }
        } else {
#pragma unroll
            for (int c = 0; c < 8; c++) xv[j][c] = 0.f;
        }
    }
    float4 wr[8];
#pragma unroll
    for (int c = 0; c < 8; c++) wr[c] = *(const float4*)(conv_w + (d0 + c) * 4);
    float bi[8];
#pragma unroll
    for (int c = 0; c < 8; c++) bi[c] = conv_b[d0 + c];

#pragma unroll
    for (int i = 0; i < 4; i++) {
        float o[8];
#pragma unroll
        for (int c = 0; c < 8; c++) {
            o[c] = bi[c] + ((const float*)&wr[c])[0] * xv[i][c]
                         + ((const float*)&wr[c])[1] * xv[i+1][c]
                         + ((const float*)&wr[c])[2] * xv[i+2][c]
                         + ((const float*)&wr[c])[3] * xv[i+3][c];
            o[c] = o[c] / (1.f + __expf(-o[c]));
        }
        uint4 v;
        v.x = pack_h2(o[0], o[1]); v.y = pack_h2(o[2], o[3]);
        v.z = pack_h2(o[4], o[5]); v.w = pack_h2(o[6], o[7]);
        *(uint4*)(g_xconv + ((size_t)(m0 + i)) * DIN + d0) = v;
    }
}

// ---------------- chunked selective scan (SEG=32) ----------------
__global__ __launch_bounds__(128) void scan_pass1(const float* __restrict__ A_log) {
    const int b = blockIdx.z;
    const int s = blockIdx.y;
    const int d = blockIdx.x * 128 + threadIdx.x;
    const int tid = threadIdx.x;
    const int l0 = s * SEGL;

    float A[NS];
    bool structured = true;
#pragma unroll
    for (int n = 0; n < NS; n++) {
        A[n] = -__expf(A_log[d * NS + n]);
        structured &= (fabsf(A[n] + (float)(n + 1)) < 1e-4f * (float)(n + 1));
    }

    float p[NS], h[NS];
#pragma unroll
    for (int n = 0; n < NS; n++) { p[n] = 1.f; h[n] = 0.f; }

    __shared__ float sB[SEGL][NS];
    for (int i = tid; i < SEGL * NS; i += 128) {
        const int ll = i >> 3;
        const int n = i & 7;
        sB[ll][n] = g_dbl[((size_t)(b * LL + l0 + ll)) * DBLW + RR + n];
    }
    __syncthreads();

    if (structured) {
        for (int j = 0; j < SEGL; j++) {
            const size_t rowb = ((size_t)(b * LL + l0 + j)) * DIN;
            const float dtv = __half2float(g_dt[rowb + d]);
            const float xv = __half2float(g_xconv[rowb + d]);
            const float dtx = dtv * xv;
            float da[NS];
            calc_da(da, dtv, A, true);
#pragma unroll
            for (int n = 0; n < NS; n++) {
                p[n] *= da[n];
                h[n] = da[n] * h[n] + dtx * sB[j][n];
            }
        }
    } else {
        for (int j = 0; j < SEGL; j++) {
            const size_t rowb = ((size_t)(b * LL + l0 + j)) * DIN;
            const float dtv = __half2float(g_dt[rowb + d]);
            const float xv = __half2float(g_xconv[rowb + d]);
            const float dtx = dtv * xv;
            float da[NS];
            calc_da(da, dtv, A, false);
#pragma unroll
            for (int n = 0; n < NS; n++) {
                p[n] *= da[n];
                h[n] = da[n] * h[n] + dtx * sB[j][n];
            }
        }
    }
#pragma unroll
    for (int n = 0; n < NS; n++) {
        const size_t o = ((size_t)((b * SEG + s) * NS + n)) * DIN + d;
        g_segA[o] = p[n];
        g_segB[o] = h[n];
    }
}

__global__ __launch_bounds__(256) void scan_pass2() {
    const int gidx = blockIdx.x * 256 + threadIdx.x;
    if (gidx >= BB * DIN) return;
    const int b = gidx / DIN;
    const int d = gidx % DIN;
    float h[NS];
#pragma unroll
    for (int n = 0; n < NS; n++) h[n] = 0.f;
    for (int s = 0; s < SEG; s++) {
#pragma unroll
        for (int n = 0; n < NS; n++) {
            const size_t o = ((size_t)((b * SEG + s) * NS + n)) * DIN + d;
            g_hin[o] = h[n];
            h[n] = g_segA[o] * h[n] + g_segB[o];
        }
    }
}

__global__ __launch_bounds__(128) void scan_pass3(const float* __restrict__ A_log,
                                                  const float* __restrict__ D_skip) {
    const int b = blockIdx.z;
    const int s = blockIdx.y;
    const int d = blockIdx.x * 128 + threadIdx.x;
    const int tid = threadIdx.x;
    const int l0 = s * SEGL;

    float A[NS];
    bool structured = true;
#pragma unroll
    for (int n = 0; n < NS; n++) {
        A[n] = -__expf(A_log[d * NS + n]);
        structured &= (fabsf(A[n] + (float)(n + 1)) < 1e-4f * (float)(n + 1));
    }
    const float dsk = D_skip[d];

    float h[NS];
#pragma unroll
    for (int n = 0; n < NS; n++)
        h[n] = g_hin[((size_t)((b * SEG + s) * NS + n)) * DIN + d];

    __shared__ float sB[SEGL][NS];
    __shared__ float sC[SEGL][NS];
    for (int i = tid; i < SEGL * NS * 2; i += 128) {
        const int ll = i >> 4;
        const int c = i & 15;
        const float v = g_dbl[((size_t)(b * LL + l0 + ll)) * DBLW + RR + c];
        if (c < NS) sB[ll][c] = v;
        else        sC[ll][c - NS] = v;
    }
    __syncthreads();

    if (structured) {
        for (int j = 0; j < SEGL; j++) {
            const size_t rowb = ((size_t)(b * LL + l0 + j)) * DIN;
            const float dtv = __half2float(g_dt[rowb + d]);
            const float xv = __half2float(g_xconv[rowb + d]);
            const float dtx = dtv * xv;
            float da[NS];
            calc_da(da, dtv, A, true);
            float yv = 0.f;
#pragma unroll
            for (int n = 0; n < NS; n++) {
                h[n] = da[n] * h[n] + dtx * sB[j][n];
                yv += h[n] * sC[j][n];
            }
            const float z = __half2float(g_xz[((size_t)(b * LL + l0 + j)) * (2 * DIN) + DIN + d]);
            const float sz = z / (1.f + __expf(-z));
            g_y[rowb + d] = __float2half_rn((yv + dsk * xv) * sz);
        }
    } else {
        for (int j = 0; j < SEGL; j++) {
            const size_t rowb = ((size_t)(b * LL + l0 + j)) * DIN;
            const float dtv = __half2float(g_dt[rowb + d]);
            const float xv = __half2float(g_xconv[rowb + d]);
            const float dtx = dtv * xv;
            float da[NS];
            calc_da(da, dtv, A, false);
            float yv = 0.f;
#pragma unroll
            for (int n = 0; n < NS; n++) {
                h[n] = da[n] * h[n] + dtx * sB[j][n];
                yv += h[n] * sC[j][n];
            }
            const float z = __half2float(g_xz[((size_t)(b * LL + l0 + j)) * (2 * DIN) + DIN + d]);
            const float sz = z / (1.f + __expf(-z));
            g_y[rowb + d] = __float2half_rn((yv + dsk * xv) * sz);
        }
    }
}

// ---------------- launch ----------------
extern "C" void kernel_launch(void* const* d_in, const int* in_sizes, int n_in,
                              void* d_out, int out_size) {
    const float* hidden = (const float*)d_in[0];
    const float* norm_w = (const float*)d_in[1];
    const float* in_proj_w = (const float*)d_in[2];
    const float* conv_w = (const float*)d_in[3];
    const float* conv_b = (const float*)d_in[4];
    const float* x_proj_w = (const float*)d_in[5];
    const float* dt_proj_w = (const float*)d_in[6];
    const float* dt_proj_b = (const float*)d_in[7];
    const float* A_log = (const float*)d_in[8];
    const float* D_skip = (const float*)d_in[9];
    const float* out_proj_w = (const float*)d_in[10];
    float* out = (float*)d_out;

    __half *p_xnorm, *p_xz, *p_xconv, *p_dblh, *p_dt, *p_y;
    __half *p_w_in, *p_w_x, *p_w_dt, *p_w_out;
    float *p_dblp;
    cudaGetSymbolAddress((void**)&p_xnorm, g_xnorm);
    cudaGetSymbolAddress((void**)&p_xz, g_xz);
    cudaGetSymbolAddress((void**)&p_xconv, g_xconv);
    cudaGetSymbolAddress((void**)&p_dblh, g_dblh);
    cudaGetSymbolAddress((void**)&p_dt, g_dt);
    cudaGetSymbolAddress((void**)&p_y, g_y);
    cudaGetSymbolAddress((void**)&p_dblp, g_dblp);
    cudaGetSymbolAddress((void**)&p_w_in, g_w_in);
    cudaGetSymbolAddress((void**)&p_w_x, g_w_x);
    cudaGetSymbolAddress((void**)&p_w_dt, g_w_dt);
    cudaGetSymbolAddress((void**)&p_w_out, g_w_out);

    cudaFuncSetAttribute(gemm_f16<__half, 0>, cudaFuncAttributeMaxDynamicSharedMemorySize, GSMEM);
    cudaFuncSetAttribute(gemm_f16<__half, 1>, cudaFuncAttributeMaxDynamicSharedMemorySize, GSMEM);
    cudaFuncSetAttribute(gemm_f16<float, 0>, cudaFuncAttributeMaxDynamicSharedMemorySize, GSMEM);

    const int M = MTOT;

    // 0a. big weights -> fp16 (launch 1)
    {
        const int total = (NWI + NWO) / 8;
        cvt_weights_big<<<(total + 255) / 256, 256>>>((const float4*)in_proj_w,
                                                      (const float4*)out_proj_w);
    }
    // 0b. small weights (launch 2)
    {
        const int total = (NWX + NWDT) / 8;
        cvt_weights_small<<<(total + 255) / 256, 256>>>((const float4*)x_proj_w,
                                                        (const float4*)dt_proj_w);
    }

    // 1. RMSNorm (launch 3)
    rmsnorm_kernel<<<M, 128>>>(hidden, norm_w);

    // 2. in_proj (launch 4 — ncu capture window) — fp16 output
    {
        dim3 grid(2 * DIN / 128, M / 128, 1);
        gemm_f16<__half, 0><<<grid, 256, GSMEM>>>(p_xnorm, DD, p_w_in, DD,
                                                  p_xz, 2 * DIN, 0, DD, 2 * DIN, nullptr);
    }

    // 3. conv + silu
    {
        const int total = (MTOT / 4) * (DIN / 8);
        conv_silu_kernel<<<(total + 255) / 256, 256>>>(conv_w, conv_b);
    }

    // 4. x_proj split-K
    {
        dim3 grid(1, M / 128, SPLITK);
        gemm_f16<float, 0><<<grid, 256, GSMEM>>>(p_xconv, DIN, p_w_x, DIN,
                                                 p_dblp, DBLW, (size_t)MTOT * DBLW,
                                                 DIN / SPLITK, DBLW, nullptr);
        reduce_dbl<<<(MTOT * DBLW + 255) / 256, 256>>>();
    }

    // 5. dt_proj + bias + softplus -> fp16 dt
    {
        dim3 grid(DIN / 128, M / 128, 1);
        gemm_f16<__half, 1><<<grid, 256, GSMEM>>>(p_dblh, DBLW, p_w_dt, RR,
                                                  p_dt, DIN, 0, RR, DIN, dt_proj_b);
    }

    // 6. selective scan
    {
        dim3 grid1(DIN / 128, SEG, BB);
        scan_pass1<<<grid1, 128>>>(A_log);
        scan_pass2<<<(BB * DIN + 255) / 256, 256>>>();
        scan_pass3<<<grid1, 128>>>(A_log, D_skip);
    }

    // 7. out_proj (fp32 output)
    {
        dim3 grid(DD / 128, M / 128, 1);
        gemm_f16<float, 0><<<grid, 256, GSMEM>>>(p_y, DIN, p_w_out, DIN,
                                                 out, DD, 0, DIN, DD, nullptr);
    }
}